// round 1
// baseline (speedup 1.0000x reference)
#include <cuda_runtime.h>
#include <cuda_bf16.h>

#define NN   50000
#define EE   1600000
#define DIN  128
#define DOUT 256
#define DA   32

// ---------------- device scratch (static, no allocations) ----------------
__device__ float  g_arow[NN * DA];          // 6.4 MB
__device__ float  g_acol[NN * DA];          // 6.4 MB
__device__ int    g_cnt [NN];
__device__ int    g_cnt2[NN];
__device__ int    g_off [NN + 1];
__device__ float4 g_edges[EE];              // {exp_a, adj_val, col*128 (bits), 0} — 25.6 MB
__device__ float  g_h[NN * DIN];            // 25.6 MB

// ---------------- kernel 0: zero counters ----------------
__global__ void zero_kernel() {
    int i = blockIdx.x * blockDim.x + threadIdx.x;
    if (i < NN) { g_cnt[i] = 0; g_cnt2[i] = 0; }
}

// ---------------- kernel 1: projections a_row = x@W_row, a_col = x@W_col ----------------
#define PROJ_NODES 16
__global__ __launch_bounds__(256) void proj_kernel(
    const float* __restrict__ x,
    const float* __restrict__ Wr,
    const float* __restrict__ Wc)
{
    __shared__ float Wsh[DIN][2 * DA];          // cols [0,32)=W_row, [32,64)=W_col
    __shared__ float xsh[PROJ_NODES][DIN + 1];
    int t = threadIdx.x;

    for (int i = t; i < DIN * DA; i += 256) {
        int k = i >> 5, j = i & 31;
        Wsh[k][j]      = Wr[i];
        Wsh[k][j + 32] = Wc[i];
    }
    int node0 = blockIdx.x * PROJ_NODES;
    for (int i = t; i < PROJ_NODES * DIN; i += 256) {
        int n = i >> 7, k = i & 127;
        int gn = node0 + n;
        xsh[n][k] = (gn < NN) ? x[gn * DIN + k] : 0.f;
    }
    __syncthreads();

    int n  = t & 15;       // local node
    int g  = t >> 4;       // output group 0..15 -> dims g*4..g*4+3
    int j0 = g * 4;
    float a0 = 0.f, a1 = 0.f, a2 = 0.f, a3 = 0.f;
#pragma unroll 8
    for (int k = 0; k < DIN; k++) {
        float xv = xsh[n][k];
        a0 += xv * Wsh[k][j0 + 0];
        a1 += xv * Wsh[k][j0 + 1];
        a2 += xv * Wsh[k][j0 + 2];
        a3 += xv * Wsh[k][j0 + 3];
    }
    int gn = node0 + n;
    if (gn < NN) {
        if (j0 < DA) {
            float* dst = &g_arow[gn * DA + j0];
            dst[0] = a0; dst[1] = a1; dst[2] = a2; dst[3] = a3;
        } else {
            float* dst = &g_acol[gn * DA + (j0 - DA)];
            dst[0] = a0; dst[1] = a1; dst[2] = a2; dst[3] = a3;
        }
    }
}

// ---------------- kernel 2: degree histogram ----------------
__global__ void hist_kernel(const int* __restrict__ row) {
    int e = blockIdx.x * blockDim.x + threadIdx.x;
    if (e < EE) atomicAdd(&g_cnt[row[e]], 1);
}

// ---------------- kernel 3: exclusive scan -> CSR offsets (single block) ----------------
__global__ __launch_bounds__(1024) void scan_kernel() {
    __shared__ int sh[1024];
    int t = threadIdx.x;
    int run = 0;
    if (t == 0) g_off[0] = 0;
    for (int base = 0; base < NN; base += 1024) {
        int i = base + t;
        int v = (i < NN) ? g_cnt[i] : 0;
        sh[t] = v;
        __syncthreads();
        for (int s = 1; s < 1024; s <<= 1) {
            int add = (t >= s) ? sh[t - s] : 0;
            __syncthreads();
            sh[t] += add;
            __syncthreads();
        }
        if (i < NN) g_off[i + 1] = run + sh[t];   // inclusive -> exclusive at i+1
        run += sh[1023];
        __syncthreads();
    }
}

// ---------------- kernel 4: per-edge attention + scatter into CSR order ----------------
// exp-shift by global max cancels through normalization -> skip it.
__global__ __launch_bounds__(256) void edge_scatter_kernel(
    const int*   __restrict__ row,
    const int*   __restrict__ col,
    const float* __restrict__ adj)
{
    int e = blockIdx.x * blockDim.x + threadIdx.x;
    if (e >= EE) return;
    int r = row[e], c = col[e];
    const float4* ar = (const float4*)&g_arow[r * DA];
    const float4* ac = (const float4*)&g_acol[c * DA];
    float dot = 0.f;
#pragma unroll
    for (int q = 0; q < DA / 4; q++) {
        float4 a = ar[q], b = ac[q];
        dot += a.x * b.x + a.y * b.y + a.z * b.z + a.w * b.w;
    }
    float s = dot * 0.17677669529663687f;      // rsqrt(32)
    if (s < 0.f) s *= 0.2f;                    // leaky relu
    float ea = __expf(s);
    int pos = g_off[r] + atomicAdd(&g_cnt2[r], 1);
    g_edges[pos] = make_float4(ea, adj[e], __int_as_float(c * DIN), 0.f);
}

// ---------------- kernel 5: per-node gather SpMM -> h [NN, 128] ----------------
__global__ __launch_bounds__(128) void spmm_kernel(const float* __restrict__ x) {
    int i   = blockIdx.x;
    int tid = threadIdx.x;            // 128 = one feature dim each
    int start = g_off[i], end = g_off[i + 1];

    __shared__ float sval[128];
    __shared__ int   scol[128];
    __shared__ float red[128];

    // softmax denominator for this row
    float ds = 0.f;
    for (int k = start + tid; k < end; k += 128) ds += g_edges[k].x;
    red[tid] = ds;
    __syncthreads();
    for (int s = 64; s > 0; s >>= 1) {
        if (tid < s) red[tid] += red[tid + s];
        __syncthreads();
    }
    float inv = 1.f / (red[0] + 1e-15f);

    float acc = 0.f;
    for (int base = start; base < end; base += 128) {
        int k = base + tid;
        __syncthreads();
        if (k < end) {
            float4 ed = g_edges[k];
            sval[tid] = (ed.y + ed.x * inv) * 0.5f;    // (adj + atten)/2
            scol[tid] = __float_as_int(ed.z);          // col*128
        }
        __syncthreads();
        int m = min(128, end - base);
#pragma unroll 4
        for (int j = 0; j < m; j++)
            acc += sval[j] * x[scol[j] + tid];
    }
    g_h[i * DIN + tid] = acc;
}

// ---------------- kernel 6: out = h @ W_x + b_x ----------------
// BM=128, BN=64, BK=16, 256 threads, 8x4 micro-tile
__global__ __launch_bounds__(256) void gemm_kernel(
    const float* __restrict__ W,
    const float* __restrict__ bias,
    float* __restrict__ out)
{
    __shared__ float As[128][17];
    __shared__ float Bs[16][64];

    int tid = threadIdx.x;
    int tx = tid & 15;     // 0..15 -> cols tx*4
    int ty = tid >> 4;     // 0..15 -> rows ty*8
    int m0 = blockIdx.y * 128;
    int n0 = blockIdx.x * 64;

    float acc[8][4];
#pragma unroll
    for (int i = 0; i < 8; i++)
#pragma unroll
        for (int j = 0; j < 4; j++) acc[i][j] = 0.f;

    for (int kk = 0; kk < DIN; kk += 16) {
        // load A (h) tile: 128x16
#pragma unroll
        for (int part = 0; part < 2; part++) {
            int lin = tid * 4 + part * 1024;
            int r = lin >> 4;            // 0..127
            int c = lin & 15;
            int gr = m0 + r;
            float4 v = make_float4(0.f, 0.f, 0.f, 0.f);
            if (gr < NN) v = *(const float4*)&g_h[gr * DIN + kk + c];
            As[r][c + 0] = v.x; As[r][c + 1] = v.y;
            As[r][c + 2] = v.z; As[r][c + 3] = v.w;
        }
        // load B (W) tile: 16x64
        {
            int lin = tid * 4;
            int r = lin >> 6;            // 0..15
            int c = lin & 63;
            float4 v = *(const float4*)&W[(kk + r) * DOUT + n0 + c];
            Bs[r][c + 0] = v.x; Bs[r][c + 1] = v.y;
            Bs[r][c + 2] = v.z; Bs[r][c + 3] = v.w;
        }
        __syncthreads();

#pragma unroll
        for (int k = 0; k < 16; k++) {
            float a[8], b[4];
#pragma unroll
            for (int i = 0; i < 8; i++) a[i] = As[ty * 8 + i][k];
#pragma unroll
            for (int j = 0; j < 4; j++) b[j] = Bs[k][tx * 4 + j];
#pragma unroll
            for (int i = 0; i < 8; i++)
#pragma unroll
                for (int j = 0; j < 4; j++) acc[i][j] += a[i] * b[j];
        }
        __syncthreads();
    }

    float bv[4];
#pragma unroll
    for (int j = 0; j < 4; j++) bv[j] = bias[n0 + tx * 4 + j];

#pragma unroll
    for (int i = 0; i < 8; i++) {
        int gr = m0 + ty * 8 + i;
        if (gr < NN) {
            float4 v = make_float4(acc[i][0] + bv[0], acc[i][1] + bv[1],
                                   acc[i][2] + bv[2], acc[i][3] + bv[3]);
            *(float4*)&out[gr * DOUT + n0 + tx * 4] = v;
        }
    }
}

// ---------------- launch ----------------
extern "C" void kernel_launch(void* const* d_in, const int* in_sizes, int n_in,
                              void* d_out, int out_size)
{
    const float* x    = (const float*)d_in[0];
    const int*   row  = (const int*)  d_in[1];
    const int*   col  = (const int*)  d_in[2];
    const float* adj  = (const float*)d_in[3];
    const float* Wr   = (const float*)d_in[4];
    const float* Wc   = (const float*)d_in[5];
    const float* Wx   = (const float*)d_in[6];
    const float* bx   = (const float*)d_in[7];
    float* out = (float*)d_out;

    zero_kernel<<<(NN + 255) / 256, 256>>>();
    proj_kernel<<<(NN + PROJ_NODES - 1) / PROJ_NODES, 256>>>(x, Wr, Wc);
    hist_kernel<<<(EE + 255) / 256, 256>>>(row);
    scan_kernel<<<1, 1024>>>();
    edge_scatter_kernel<<<(EE + 255) / 256, 256>>>(row, col, adj);
    spmm_kernel<<<NN, 128>>>(x);
    gemm_kernel<<<dim3(DOUT / 64, (NN + 127) / 128), 256>>>(Wx, bx, out);
}

// round 2
// speedup vs baseline: 1.1920x; 1.1920x over previous
#include <cuda_runtime.h>
#include <cuda_bf16.h>

#define NN   50000
#define EE   1600000
#define DIN  128
#define DOUT 256
#define DA   32
#define NBLK ((NN + 1023) / 1024)   // 49

// ---------------- device scratch (static, no allocations) ----------------
__device__ float  g_arow[NN * DA];          // 6.4 MB
__device__ float  g_acol[NN * DA];          // 6.4 MB
__device__ int    g_cnt [NN];
__device__ int    g_cnt2[NN];
__device__ int    g_off [NN + 1];
__device__ int    g_bsum[NBLK];
__device__ float4 g_edges[EE];              // {exp_a, adj_val, col*128 (bits), 0} — 25.6 MB
__device__ float  g_h[NN * DIN];            // 25.6 MB

// ---------------- kernel 0: zero counters ----------------
__global__ void zero_kernel() {
    int i = blockIdx.x * blockDim.x + threadIdx.x;
    if (i < NN) { g_cnt[i] = 0; g_cnt2[i] = 0; }
}

// ---------------- kernel 1: projections a_row = x@W_row, a_col = x@W_col ----------------
#define PROJ_NODES 16
__global__ __launch_bounds__(256) void proj_kernel(
    const float* __restrict__ x,
    const float* __restrict__ Wr,
    const float* __restrict__ Wc)
{
    __shared__ float Wsh[DIN][2 * DA];          // cols [0,32)=W_row, [32,64)=W_col
    __shared__ float xsh[PROJ_NODES][DIN + 1];
    int t = threadIdx.x;

    for (int i = t; i < DIN * DA; i += 256) {
        int k = i >> 5, j = i & 31;
        Wsh[k][j]      = Wr[i];
        Wsh[k][j + 32] = Wc[i];
    }
    int node0 = blockIdx.x * PROJ_NODES;
    for (int i = t; i < PROJ_NODES * DIN; i += 256) {
        int n = i >> 7, k = i & 127;
        int gn = node0 + n;
        xsh[n][k] = (gn < NN) ? x[gn * DIN + k] : 0.f;
    }
    __syncthreads();

    int n  = t & 15;       // local node
    int g  = t >> 4;       // output group 0..15 -> dims g*4..g*4+3
    int j0 = g * 4;
    float a0 = 0.f, a1 = 0.f, a2 = 0.f, a3 = 0.f;
#pragma unroll 8
    for (int k = 0; k < DIN; k++) {
        float xv = xsh[n][k];
        a0 += xv * Wsh[k][j0 + 0];
        a1 += xv * Wsh[k][j0 + 1];
        a2 += xv * Wsh[k][j0 + 2];
        a3 += xv * Wsh[k][j0 + 3];
    }
    int gn = node0 + n;
    if (gn < NN) {
        if (j0 < DA) {
            float* dst = &g_arow[gn * DA + j0];
            dst[0] = a0; dst[1] = a1; dst[2] = a2; dst[3] = a3;
        } else {
            float* dst = &g_acol[gn * DA + (j0 - DA)];
            dst[0] = a0; dst[1] = a1; dst[2] = a2; dst[3] = a3;
        }
    }
}

// ---------------- kernel 2: degree histogram ----------------
__global__ void hist_kernel(const int* __restrict__ row) {
    int e = blockIdx.x * blockDim.x + threadIdx.x;
    if (e < EE) atomicAdd(&g_cnt[row[e]], 1);
}

// ---------------- kernels 3a/3b/3c: two-level exclusive scan -> CSR offsets ----------------
__global__ __launch_bounds__(1024) void scanA_kernel() {
    __shared__ int wsum[32];
    int b = blockIdx.x, t = threadIdx.x;
    int i = b * 1024 + t;
    int lane = t & 31, w = t >> 5;
    int v = (i < NN) ? g_cnt[i] : 0;
    int s = v;
#pragma unroll
    for (int d = 1; d < 32; d <<= 1) {
        int n = __shfl_up_sync(0xffffffffu, s, d);
        if (lane >= d) s += n;
    }
    if (lane == 31) wsum[w] = s;
    __syncthreads();
    if (w == 0) {
        int ws = wsum[lane];
#pragma unroll
        for (int d = 1; d < 32; d <<= 1) {
            int n = __shfl_up_sync(0xffffffffu, ws, d);
            if (lane >= d) ws += n;
        }
        wsum[lane] = ws;
    }
    __syncthreads();
    int incl = s + (w > 0 ? wsum[w - 1] : 0);
    if (i < NN) g_off[i + 1] = incl;          // block-local inclusive
    if (t == 1023) g_bsum[b] = incl;          // block total
}

__global__ void scanB_kernel() {
    __shared__ int sh[64];
    int t = threadIdx.x;
    sh[t] = (t < NBLK) ? g_bsum[t] : 0;
    __syncthreads();
#pragma unroll
    for (int s = 1; s < 64; s <<= 1) {
        int a = (t >= s) ? sh[t - s] : 0;
        __syncthreads();
        sh[t] += a;
        __syncthreads();
    }
    if (t < NBLK) g_bsum[t] = sh[t];          // inclusive block prefix
}

__global__ __launch_bounds__(1024) void scanC_kernel() {
    int b = blockIdx.x, t = threadIdx.x;
    int i = b * 1024 + t;
    int add = (b > 0) ? g_bsum[b - 1] : 0;
    if (i < NN) g_off[i + 1] += add;
    if (b == 0 && t == 0) g_off[0] = 0;
}

// ---------------- kernel 4: per-edge attention + scatter into CSR order ----------------
// exp-shift by global max cancels through normalization -> skip it.
__global__ __launch_bounds__(256) void edge_scatter_kernel(
    const int*   __restrict__ row,
    const int*   __restrict__ col,
    const float* __restrict__ adj)
{
    int e = blockIdx.x * blockDim.x + threadIdx.x;
    if (e >= EE) return;
    int r = row[e], c = col[e];
    const float4* ar = (const float4*)&g_arow[r * DA];
    const float4* ac = (const float4*)&g_acol[c * DA];
    float dot = 0.f;
#pragma unroll
    for (int q = 0; q < DA / 4; q++) {
        float4 a = ar[q], b = ac[q];
        dot += a.x * b.x + a.y * b.y + a.z * b.z + a.w * b.w;
    }
    float s = dot * 0.17677669529663687f;      // rsqrt(32)
    if (s < 0.f) s *= 0.2f;                    // leaky relu
    float ea = __expf(s);
    int pos = g_off[r] + atomicAdd(&g_cnt2[r], 1);
    g_edges[pos] = make_float4(ea, adj[e], __int_as_float(c * DIN), 0.f);
}

// ---------------- kernel 5: per-node gather SpMM -> h [NN, 128] ----------------
__global__ __launch_bounds__(128) void spmm_kernel(const float* __restrict__ x) {
    int i   = blockIdx.x;
    int tid = threadIdx.x;            // 128 = one feature dim each
    int lane = tid & 31, w = tid >> 5;
    int start = g_off[i], end = g_off[i + 1];

    __shared__ float sval[128];
    __shared__ int   scol[128];
    __shared__ float red[4];

    // softmax denominator for this row (warp-shuffle reduce)
    float ds = 0.f;
    for (int k = start + tid; k < end; k += 128) ds += g_edges[k].x;
#pragma unroll
    for (int s = 16; s > 0; s >>= 1) ds += __shfl_xor_sync(0xffffffffu, ds, s);
    if (lane == 0) red[w] = ds;
    __syncthreads();
    float inv = 1.f / (red[0] + red[1] + red[2] + red[3] + 1e-15f);

    float acc = 0.f;
    for (int base = start; base < end; base += 128) {
        int k = base + tid;
        __syncthreads();
        if (k < end) {
            float4 ed = g_edges[k];
            sval[tid] = (ed.y + ed.x * inv) * 0.5f;    // (adj + atten)/2
            scol[tid] = __float_as_int(ed.z);          // col*128
        }
        __syncthreads();
        int m = min(128, end - base);
#pragma unroll 8
        for (int j = 0; j < m; j++)
            acc += sval[j] * x[scol[j] + tid];
    }
    g_h[i * DIN + tid] = acc;
}

// ---------------- kernel 6: out = h @ W_x + b_x ----------------
// BM=128, BN=64, BK=16, 256 threads, 8x4 micro-tile
__global__ __launch_bounds__(256) void gemm_kernel(
    const float* __restrict__ W,
    const float* __restrict__ bias,
    float* __restrict__ out)
{
    __shared__ float As[128][17];
    __shared__ float Bs[16][64];

    int tid = threadIdx.x;
    int tx = tid & 15;     // 0..15 -> cols tx*4
    int ty = tid >> 4;     // 0..15 -> rows ty*8
    int m0 = blockIdx.y * 128;
    int n0 = blockIdx.x * 64;

    float acc[8][4];
#pragma unroll
    for (int i = 0; i < 8; i++)
#pragma unroll
        for (int j = 0; j < 4; j++) acc[i][j] = 0.f;

    for (int kk = 0; kk < DIN; kk += 16) {
        // load A (h) tile: 128x16
#pragma unroll
        for (int part = 0; part < 2; part++) {
            int lin = tid * 4 + part * 1024;
            int r = lin >> 4;            // 0..127
            int c = lin & 15;
            int gr = m0 + r;
            float4 v = make_float4(0.f, 0.f, 0.f, 0.f);
            if (gr < NN) v = *(const float4*)&g_h[gr * DIN + kk + c];
            As[r][c + 0] = v.x; As[r][c + 1] = v.y;
            As[r][c + 2] = v.z; As[r][c + 3] = v.w;
        }
        // load B (W) tile: 16x64
        {
            int lin = tid * 4;
            int r = lin >> 6;            // 0..15
            int c = lin & 63;
            float4 v = *(const float4*)&W[(kk + r) * DOUT + n0 + c];
            Bs[r][c + 0] = v.x; Bs[r][c + 1] = v.y;
            Bs[r][c + 2] = v.z; Bs[r][c + 3] = v.w;
        }
        __syncthreads();

#pragma unroll
        for (int k = 0; k < 16; k++) {
            float a[8], b[4];
#pragma unroll
            for (int i = 0; i < 8; i++) a[i] = As[ty * 8 + i][k];
#pragma unroll
            for (int j = 0; j < 4; j++) b[j] = Bs[k][tx * 4 + j];
#pragma unroll
            for (int i = 0; i < 8; i++)
#pragma unroll
                for (int j = 0; j < 4; j++) acc[i][j] += a[i] * b[j];
        }
        __syncthreads();
    }

    float bv[4];
#pragma unroll
    for (int j = 0; j < 4; j++) bv[j] = bias[n0 + tx * 4 + j];

#pragma unroll
    for (int i = 0; i < 8; i++) {
        int gr = m0 + ty * 8 + i;
        if (gr < NN) {
            float4 v = make_float4(acc[i][0] + bv[0], acc[i][1] + bv[1],
                                   acc[i][2] + bv[2], acc[i][3] + bv[3]);
            *(float4*)&out[gr * DOUT + n0 + tx * 4] = v;
        }
    }
}

// ---------------- launch ----------------
extern "C" void kernel_launch(void* const* d_in, const int* in_sizes, int n_in,
                              void* d_out, int out_size)
{
    const float* x    = (const float*)d_in[0];
    const int*   row  = (const int*)  d_in[1];
    const int*   col  = (const int*)  d_in[2];
    const float* adj  = (const float*)d_in[3];
    const float* Wr   = (const float*)d_in[4];
    const float* Wc   = (const float*)d_in[5];
    const float* Wx   = (const float*)d_in[6];
    const float* bx   = (const float*)d_in[7];
    float* out = (float*)d_out;

    zero_kernel<<<(NN + 255) / 256, 256>>>();
    proj_kernel<<<(NN + PROJ_NODES - 1) / PROJ_NODES, 256>>>(x, Wr, Wc);
    hist_kernel<<<(EE + 255) / 256, 256>>>(row);
    scanA_kernel<<<NBLK, 1024>>>();
    scanB_kernel<<<1, 64>>>();
    scanC_kernel<<<NBLK, 1024>>>();
    edge_scatter_kernel<<<(EE + 255) / 256, 256>>>(row, col, adj);
    spmm_kernel<<<NN, 128>>>(x);
    gemm_kernel<<<dim3(DOUT / 64, (NN + 127) / 128), 256>>>(Wx, bx, out);
}

// round 4
// speedup vs baseline: 1.4929x; 1.2525x over previous
#include <cuda_runtime.h>
#include <cuda_fp16.h>
#include <cuda_bf16.h>

#define NN   50000
#define EE   1600000
#define DIN  128
#define DOUT 256
#define DA   32
#define NBLK ((NN + 1023) / 1024)   // 49

typedef unsigned long long ull;

// ---------------- device scratch (static, no allocations) ----------------
__device__ __half2 g_arowh[NN * 16];        // a_row as half2 (3.2 MB)
__device__ __half2 g_acolh[NN * 16];        // a_col as half2 (3.2 MB)
__device__ __half2 g_xh[NN * 64];           // x as half2     (12.8 MB)
__device__ float  g_deg[NN];
__device__ int    g_cnt [NN];
__device__ int    g_cnt2[NN];
__device__ int    g_off [NN + 1];
__device__ int    g_bsum[NBLK];
__device__ float4 g_edges[EE];              // {exp_a, adj_val, col*64 (bits), 0}
__device__ float  g_h[NN * DIN];            // 25.6 MB

// ---------------- kernel 0: zero counters ----------------
__global__ void zero_kernel() {
    int i = blockIdx.x * blockDim.x + threadIdx.x;
    if (i < NN) { g_cnt[i] = 0; g_cnt2[i] = 0; g_deg[i] = 0.f; }
}

// ---------------- kernel 1: projections + x->half2 convert ----------------
#define PROJ_NODES 16
__global__ __launch_bounds__(256) void proj_kernel(
    const float* __restrict__ x,
    const float* __restrict__ Wr,
    const float* __restrict__ Wc)
{
    __shared__ float Wsh[DIN][2 * DA];          // cols [0,32)=W_row, [32,64)=W_col
    __shared__ float xsh[PROJ_NODES][DIN + 1];
    int t = threadIdx.x;

    for (int i = t; i < DIN * DA; i += 256) {
        int k = i >> 5, j = i & 31;
        Wsh[k][j]      = Wr[i];
        Wsh[k][j + 32] = Wc[i];
    }
    int node0 = blockIdx.x * PROJ_NODES;
    for (int i = t; i < PROJ_NODES * DIN; i += 256) {
        int n = i >> 7, k = i & 127;
        int gn = node0 + n;
        xsh[n][k] = (gn < NN) ? x[gn * DIN + k] : 0.f;
    }
    __syncthreads();

    // write x as half2 (free conversion: x already staged in smem)
    for (int i = t; i < PROJ_NODES * 64; i += 256) {
        int n = i >> 6, k2 = i & 63;
        int gn = node0 + n;
        if (gn < NN)
            g_xh[gn * 64 + k2] = __floats2half2_rn(xsh[n][2 * k2], xsh[n][2 * k2 + 1]);
    }

    int n  = t & 15;       // local node
    int g  = t >> 4;       // output group 0..15 -> dims g*4..g*4+3
    int j0 = g * 4;
    float a0 = 0.f, a1 = 0.f, a2 = 0.f, a3 = 0.f;
#pragma unroll 8
    for (int k = 0; k < DIN; k++) {
        float xv = xsh[n][k];
        a0 += xv * Wsh[k][j0 + 0];
        a1 += xv * Wsh[k][j0 + 1];
        a2 += xv * Wsh[k][j0 + 2];
        a3 += xv * Wsh[k][j0 + 3];
    }
    int gn = node0 + n;
    if (gn < NN) {
        if (j0 < DA) {
            g_arowh[gn * 16 + (j0 >> 1)]     = __floats2half2_rn(a0, a1);
            g_arowh[gn * 16 + (j0 >> 1) + 1] = __floats2half2_rn(a2, a3);
        } else {
            int j = j0 - DA;
            g_acolh[gn * 16 + (j >> 1)]      = __floats2half2_rn(a0, a1);
            g_acolh[gn * 16 + (j >> 1) + 1]  = __floats2half2_rn(a2, a3);
        }
    }
}

// ---------------- kernel 2: degree histogram ----------------
__global__ void hist_kernel(const int* __restrict__ row) {
    int e = blockIdx.x * blockDim.x + threadIdx.x;
    if (e < EE) atomicAdd(&g_cnt[row[e]], 1);
}

// ---------------- kernels 3a/3b/3c: two-level exclusive scan -> CSR offsets ----------------
__global__ __launch_bounds__(1024) void scanA_kernel() {
    __shared__ int wsum[32];
    int b = blockIdx.x, t = threadIdx.x;
    int i = b * 1024 + t;
    int lane = t & 31, w = t >> 5;
    int v = (i < NN) ? g_cnt[i] : 0;
    int s = v;
#pragma unroll
    for (int d = 1; d < 32; d <<= 1) {
        int n = __shfl_up_sync(0xffffffffu, s, d);
        if (lane >= d) s += n;
    }
    if (lane == 31) wsum[w] = s;
    __syncthreads();
    if (w == 0) {
        int ws = wsum[lane];
#pragma unroll
        for (int d = 1; d < 32; d <<= 1) {
            int n = __shfl_up_sync(0xffffffffu, ws, d);
            if (lane >= d) ws += n;
        }
        wsum[lane] = ws;
    }
    __syncthreads();
    int incl = s + (w > 0 ? wsum[w - 1] : 0);
    if (i < NN) g_off[i + 1] = incl;          // block-local inclusive
    if (t == 1023) g_bsum[b] = incl;          // block total
}

__global__ void scanB_kernel() {
    __shared__ int sh[64];
    int t = threadIdx.x;
    sh[t] = (t < NBLK) ? g_bsum[t] : 0;
    __syncthreads();
#pragma unroll
    for (int s = 1; s < 64; s <<= 1) {
        int a = (t >= s) ? sh[t - s] : 0;
        __syncthreads();
        sh[t] += a;
        __syncthreads();
    }
    if (t < NBLK) g_bsum[t] = sh[t];          // inclusive block prefix
}

__global__ __launch_bounds__(1024) void scanC_kernel() {
    int b = blockIdx.x, t = threadIdx.x;
    int i = b * 1024 + t;
    int add = (b > 0) ? g_bsum[b - 1] : 0;
    if (i < NN) g_off[i + 1] += add;
    if (b == 0 && t == 0) g_off[0] = 0;
}

// ---------------- kernel 4: per-edge attention + scatter into CSR order ----------------
// exp-shift by global max cancels through normalization -> skip it.
// also accumulates softmax denominator per row via atomics.
__global__ __launch_bounds__(256) void edge_scatter_kernel(
    const int*   __restrict__ row,
    const int*   __restrict__ col,
    const float* __restrict__ adj)
{
    int e = blockIdx.x * blockDim.x + threadIdx.x;
    if (e >= EE) return;
    int r = row[e], c = col[e];
    const uint4* ar4 = (const uint4*)&g_arowh[r * 16];
    const uint4* ac4 = (const uint4*)&g_acolh[c * 16];
    float dot = 0.f;
#pragma unroll
    for (int q = 0; q < 4; q++) {              // 4 x uint4 = 64 B = all 32 dims
        uint4 A = ar4[q], B = ac4[q];
        const __half2* ah = (const __half2*)&A;
        const __half2* bh = (const __half2*)&B;
#pragma unroll
        for (int j = 0; j < 4; j++) {
            float2 a = __half22float2(ah[j]);
            float2 b = __half22float2(bh[j]);
            dot += a.x * b.x + a.y * b.y;
        }
    }
    float s = dot * 0.17677669529663687f;      // rsqrt(32)
    if (s < 0.f) s *= 0.2f;                    // leaky relu
    float ea = __expf(s);
    atomicAdd(&g_deg[r], ea);
    int pos = g_off[r] + atomicAdd(&g_cnt2[r], 1);
    g_edges[pos] = make_float4(ea, adj[e], __int_as_float(c * 64), 0.f);
}

// ---------------- kernel 5: per-node gather SpMM (half2 x) -> h [NN, 128] ----------------
__global__ __launch_bounds__(64) void spmm_kernel() {
    int i   = blockIdx.x;
    int tid = threadIdx.x;            // 64 threads = one half2 (2 dims) each
    int start = g_off[i], end = g_off[i + 1];

    __shared__ float sval[64];
    __shared__ int   scol[64];

    float inv = 1.f / (g_deg[i] + 1e-15f);

    float accx = 0.f, accy = 0.f;
    for (int base = start; base < end; base += 64) {
        int k = base + tid;
        __syncthreads();
        if (k < end) {
            float4 ed = g_edges[k];
            sval[tid] = (ed.y + ed.x * inv) * 0.5f;    // (adj + atten)/2
            scol[tid] = __float_as_int(ed.z);          // col*64
        }
        __syncthreads();
        int m = min(64, end - base);
#pragma unroll 8
        for (int j = 0; j < m; j++) {
            float  v  = sval[j];
            float2 xf = __half22float2(g_xh[scol[j] + tid]);
            accx += v * xf.x;
            accy += v * xf.y;
        }
    }
    *(float2*)&g_h[i * DIN + 2 * tid] = make_float2(accx, accy);
}

// ---------------- kernel 6: out = h @ W_x + b_x (f32x2 packed FFMA) ----------------
// BM=128, BN=64, BK=16, 256 threads, 8x4 micro-tile
__global__ __launch_bounds__(256) void gemm_kernel(
    const float* __restrict__ W,
    const float* __restrict__ bias,
    float* __restrict__ out)
{
    __shared__ float As[128][17];
    __shared__ float Bs[16][64];

    int tid = threadIdx.x;
    int tx = tid & 15;     // 0..15 -> cols tx*4
    int ty = tid >> 4;     // 0..15 -> rows ty*8
    int m0 = blockIdx.y * 128;
    int n0 = blockIdx.x * 64;

    ull acc01[8], acc23[8];
#pragma unroll
    for (int i = 0; i < 8; i++) { acc01[i] = 0ull; acc23[i] = 0ull; }

    for (int kk = 0; kk < DIN; kk += 16) {
        // load A (h) tile: 128x16
#pragma unroll
        for (int part = 0; part < 2; part++) {
            int lin = tid * 4 + part * 1024;
            int r = lin >> 4;            // 0..127
            int c = lin & 15;
            int gr = m0 + r;
            float4 v = make_float4(0.f, 0.f, 0.f, 0.f);
            if (gr < NN) v = *(const float4*)&g_h[gr * DIN + kk + c];
            As[r][c + 0] = v.x; As[r][c + 1] = v.y;
            As[r][c + 2] = v.z; As[r][c + 3] = v.w;
        }
        // load B (W) tile: 16x64
        {
            int lin = tid * 4;
            int r = lin >> 6;            // 0..15
            int c = lin & 63;
            float4 v = *(const float4*)&W[(kk + r) * DOUT + n0 + c];
            Bs[r][c + 0] = v.x; Bs[r][c + 1] = v.y;
            Bs[r][c + 2] = v.z; Bs[r][c + 3] = v.w;
        }
        __syncthreads();

#pragma unroll
        for (int k = 0; k < 16; k++) {
            // b pair loads: contiguous -> already packed f32x2
            ull b01 = *(const ull*)&Bs[k][tx * 4 + 0];
            ull b23 = *(const ull*)&Bs[k][tx * 4 + 2];
#pragma unroll
            for (int i = 0; i < 8; i++) {
                float a = As[ty * 8 + i][k];
                ull aa;
                asm("mov.b64 %0, {%1, %1};" : "=l"(aa) : "r"(__float_as_uint(a)));
                asm("fma.rn.f32x2 %0, %1, %2, %0;" : "+l"(acc01[i]) : "l"(aa), "l"(b01));
                asm("fma.rn.f32x2 %0, %1, %2, %0;" : "+l"(acc23[i]) : "l"(aa), "l"(b23));
            }
        }
        __syncthreads();
    }

    float bv[4];
#pragma unroll
    for (int j = 0; j < 4; j++) bv[j] = bias[n0 + tx * 4 + j];

#pragma unroll
    for (int i = 0; i < 8; i++) {
        int gr = m0 + ty * 8 + i;
        if (gr < NN) {
            unsigned lo0, hi0, lo1, hi1;
            asm("mov.b64 {%0, %1}, %2;" : "=r"(lo0), "=r"(hi0) : "l"(acc01[i]));
            asm("mov.b64 {%0, %1}, %2;" : "=r"(lo1), "=r"(hi1) : "l"(acc23[i]));
            float4 v = make_float4(__uint_as_float(lo0) + bv[0],
                                   __uint_as_float(hi0) + bv[1],
                                   __uint_as_float(lo1) + bv[2],
                                   __uint_as_float(hi1) + bv[3]);
            *(float4*)&out[gr * DOUT + n0 + tx * 4] = v;
        }
    }
}

// ---------------- launch ----------------
extern "C" void kernel_launch(void* const* d_in, const int* in_sizes, int n_in,
                              void* d_out, int out_size)
{
    const float* x    = (const float*)d_in[0];
    const int*   row  = (const int*)  d_in[1];
    const int*   col  = (const int*)  d_in[2];
    const float* adj  = (const float*)d_in[3];
    const float* Wr   = (const float*)d_in[4];
    const float* Wc   = (const float*)d_in[5];
    const float* Wx   = (const float*)d_in[6];
    const float* bx   = (const float*)d_in[7];
    float* out = (float*)d_out;

    zero_kernel<<<(NN + 255) / 256, 256>>>();
    proj_kernel<<<(NN + PROJ_NODES - 1) / PROJ_NODES, 256>>>(x, Wr, Wc);
    hist_kernel<<<(EE + 255) / 256, 256>>>(row);
    scanA_kernel<<<NBLK, 1024>>>();
    scanB_kernel<<<1, 64>>>();
    scanC_kernel<<<NBLK, 1024>>>();
    edge_scatter_kernel<<<(EE + 255) / 256, 256>>>(row, col, adj);
    spmm_kernel<<<NN, 64>>>();
    gemm_kernel<<<dim3(DOUT / 64, (NN + 127) / 128), 256>>>(Wx, bx, out);
}

// round 5
// speedup vs baseline: 1.9494x; 1.3058x over previous
#include <cuda_runtime.h>
#include <cuda_fp16.h>
#include <cuda_bf16.h>

#define NN   50000
#define EE   1600000
#define DIN  128
#define DOUT 256
#define DA   32
#define NBLK ((NN + 1023) / 1024)   // 49

typedef unsigned long long ull;

// ---------------- device scratch (static, no allocations) ----------------
__device__ __half2 g_arowh[NN * 16];        // a_row as half2 (3.2 MB)
__device__ __half2 g_acolh[NN * 16];        // a_col as half2 (3.2 MB)
__device__ __half2 g_xh[NN * 64];           // x as half2     (12.8 MB)
__device__ __half2 g_hh[NN * 64];           // h as half2     (12.8 MB)
__device__ __half  g_Wh[DIN * DOUT];        // W_x as half    (64 KB)
__device__ float  g_deg[NN];
__device__ int    g_cnt [NN];
__device__ int    g_cnt2[NN];
__device__ int    g_off [NN + 1];
__device__ int    g_bsum[NBLK];
__device__ float4 g_edges[EE];              // {exp_a, adj_val, col*64 (bits), 0}

// ---------------- kernel 0: zero counters ----------------
__global__ void zero_kernel() {
    int i = blockIdx.x * blockDim.x + threadIdx.x;
    if (i < NN) { g_cnt[i] = 0; g_cnt2[i] = 0; g_deg[i] = 0.f; }
}

// ---------------- kernel 0b: convert W_x to fp16 ----------------
__global__ void wconv_kernel(const float* __restrict__ W) {
    int i = blockIdx.x * blockDim.x + threadIdx.x;
    if (i < DIN * DOUT) g_Wh[i] = __float2half(W[i]);
}

// ---------------- kernel 1: projections + x->half2 convert ----------------
#define PROJ_NODES 16
__global__ __launch_bounds__(256) void proj_kernel(
    const float* __restrict__ x,
    const float* __restrict__ Wr,
    const float* __restrict__ Wc)
{
    __shared__ float Wsh[DIN][2 * DA];          // cols [0,32)=W_row, [32,64)=W_col
    __shared__ float xsh[PROJ_NODES][DIN + 1];
    int t = threadIdx.x;

    for (int i = t; i < DIN * DA; i += 256) {
        int k = i >> 5, j = i & 31;
        Wsh[k][j]      = Wr[i];
        Wsh[k][j + 32] = Wc[i];
    }
    int node0 = blockIdx.x * PROJ_NODES;
    for (int i = t; i < PROJ_NODES * DIN; i += 256) {
        int n = i >> 7, k = i & 127;
        int gn = node0 + n;
        xsh[n][k] = (gn < NN) ? x[gn * DIN + k] : 0.f;
    }
    __syncthreads();

    // write x as half2 (free conversion: x already staged in smem)
    for (int i = t; i < PROJ_NODES * 64; i += 256) {
        int n = i >> 6, k2 = i & 63;
        int gn = node0 + n;
        if (gn < NN)
            g_xh[gn * 64 + k2] = __floats2half2_rn(xsh[n][2 * k2], xsh[n][2 * k2 + 1]);
    }

    int n  = t & 15;       // local node
    int g  = t >> 4;       // output group 0..15 -> dims g*4..g*4+3
    int j0 = g * 4;
    float a0 = 0.f, a1 = 0.f, a2 = 0.f, a3 = 0.f;
#pragma unroll 8
    for (int k = 0; k < DIN; k++) {
        float xv = xsh[n][k];
        a0 += xv * Wsh[k][j0 + 0];
        a1 += xv * Wsh[k][j0 + 1];
        a2 += xv * Wsh[k][j0 + 2];
        a3 += xv * Wsh[k][j0 + 3];
    }
    int gn = node0 + n;
    if (gn < NN) {
        if (j0 < DA) {
            g_arowh[gn * 16 + (j0 >> 1)]     = __floats2half2_rn(a0, a1);
            g_arowh[gn * 16 + (j0 >> 1) + 1] = __floats2half2_rn(a2, a3);
        } else {
            int j = j0 - DA;
            g_acolh[gn * 16 + (j >> 1)]      = __floats2half2_rn(a0, a1);
            g_acolh[gn * 16 + (j >> 1) + 1]  = __floats2half2_rn(a2, a3);
        }
    }
}

// ---------------- kernel 2: degree histogram ----------------
__global__ void hist_kernel(const int* __restrict__ row) {
    int e = blockIdx.x * blockDim.x + threadIdx.x;
    if (e < EE) atomicAdd(&g_cnt[row[e]], 1);
}

// ---------------- kernels 3a/3b/3c: two-level exclusive scan -> CSR offsets ----------------
__global__ __launch_bounds__(1024) void scanA_kernel() {
    __shared__ int wsum[32];
    int b = blockIdx.x, t = threadIdx.x;
    int i = b * 1024 + t;
    int lane = t & 31, w = t >> 5;
    int v = (i < NN) ? g_cnt[i] : 0;
    int s = v;
#pragma unroll
    for (int d = 1; d < 32; d <<= 1) {
        int n = __shfl_up_sync(0xffffffffu, s, d);
        if (lane >= d) s += n;
    }
    if (lane == 31) wsum[w] = s;
    __syncthreads();
    if (w == 0) {
        int ws = wsum[lane];
#pragma unroll
        for (int d = 1; d < 32; d <<= 1) {
            int n = __shfl_up_sync(0xffffffffu, ws, d);
            if (lane >= d) ws += n;
        }
        wsum[lane] = ws;
    }
    __syncthreads();
    int incl = s + (w > 0 ? wsum[w - 1] : 0);
    if (i < NN) g_off[i + 1] = incl;          // block-local inclusive
    if (t == 1023) g_bsum[b] = incl;          // block total
}

__global__ void scanB_kernel() {
    __shared__ int sh[64];
    int t = threadIdx.x;
    sh[t] = (t < NBLK) ? g_bsum[t] : 0;
    __syncthreads();
#pragma unroll
    for (int s = 1; s < 64; s <<= 1) {
        int a = (t >= s) ? sh[t - s] : 0;
        __syncthreads();
        sh[t] += a;
        __syncthreads();
    }
    if (t < NBLK) g_bsum[t] = sh[t];          // inclusive block prefix
}

__global__ __launch_bounds__(1024) void scanC_kernel() {
    int b = blockIdx.x, t = threadIdx.x;
    int i = b * 1024 + t;
    int add = (b > 0) ? g_bsum[b - 1] : 0;
    if (i < NN) g_off[i + 1] += add;
    if (b == 0 && t == 0) g_off[0] = 0;
}

// ---------------- kernel 4: per-edge attention + scatter into CSR order ----------------
__global__ __launch_bounds__(256) void edge_scatter_kernel(
    const int*   __restrict__ row,
    const int*   __restrict__ col,
    const float* __restrict__ adj)
{
    int e = blockIdx.x * blockDim.x + threadIdx.x;
    if (e >= EE) return;
    int r = row[e], c = col[e];
    const uint4* ar4 = (const uint4*)&g_arowh[r * 16];
    const uint4* ac4 = (const uint4*)&g_acolh[c * 16];
    float dot = 0.f;
#pragma unroll
    for (int q = 0; q < 4; q++) {              // 4 x uint4 = 64 B = all 32 dims
        uint4 A = ar4[q], B = ac4[q];
        const __half2* ah = (const __half2*)&A;
        const __half2* bh = (const __half2*)&B;
#pragma unroll
        for (int j = 0; j < 4; j++) {
            float2 a = __half22float2(ah[j]);
            float2 b = __half22float2(bh[j]);
            dot += a.x * b.x + a.y * b.y;
        }
    }
    float s = dot * 0.17677669529663687f;      // rsqrt(32)
    if (s < 0.f) s *= 0.2f;                    // leaky relu
    float ea = __expf(s);
    atomicAdd(&g_deg[r], ea);
    int pos = g_off[r] + atomicAdd(&g_cnt2[r], 1);
    g_edges[pos] = make_float4(ea, adj[e], __int_as_float(c * 64), 0.f);
}

// ---------------- kernel 5: per-node gather SpMM (half2 x) -> h fp16 ----------------
__global__ __launch_bounds__(64) void spmm_kernel() {
    int i   = blockIdx.x;
    int tid = threadIdx.x;            // 64 threads = one half2 (2 dims) each
    int start = g_off[i], end = g_off[i + 1];

    __shared__ float sval[64];
    __shared__ int   scol[64];

    float inv = 1.f / (g_deg[i] + 1e-15f);

    float accx = 0.f, accy = 0.f;
    for (int base = start; base < end; base += 64) {
        int k = base + tid;
        __syncthreads();
        if (k < end) {
            float4 ed = g_edges[k];
            sval[tid] = (ed.y + ed.x * inv) * 0.5f;    // (adj + atten)/2
            scol[tid] = __float_as_int(ed.z);          // col*64
        }
        __syncthreads();
        int m = min(64, end - base);
#pragma unroll 8
        for (int j = 0; j < m; j++) {
            float  v  = sval[j];
            float2 xf = __half22float2(g_xh[scol[j] + tid]);
            accx += v * xf.x;
            accy += v * xf.y;
        }
    }
    g_hh[i * 64 + tid] = __floats2half2_rn(accx, accy);
}

// ---------------- kernel 6: out = h @ W_x + b_x (HMMA m16n8k16) ----------------
// BM=128, BN=128, single K=128 pass. 256 threads (8 warps), warp tile 32x64.
#define LDA 136
#define LDB 136
__global__ __launch_bounds__(256) void gemm_kernel(
    const float* __restrict__ bias,
    float* __restrict__ out)
{
    extern __shared__ __half sm[];
    __half* As = sm;                 // [128][LDA]
    __half* Bs = sm + 128 * LDA;     // [128][LDB]

    int tid = threadIdx.x;
    int m0  = blockIdx.y * 128;
    int n0g = blockIdx.x * 128;

    // load A: h rows m0..m0+127 (256 B each = 16 uint4)
    const uint4* hsrc = (const uint4*)g_hh;
#pragma unroll
    for (int p = 0; p < 8; p++) {
        int idx = tid + 256 * p;
        int r = idx >> 4, seg = idx & 15;
        uint4 v = make_uint4(0u, 0u, 0u, 0u);
        if (m0 + r < NN) v = hsrc[(m0 + r) * 16 + seg];
        *(uint4*)&As[r * LDA + seg * 8] = v;
    }
    // load B: W rows k=0..127, cols n0g..n0g+127 (16 uint4 per row slice)
    const uint4* wsrc = (const uint4*)g_Wh;
#pragma unroll
    for (int p = 0; p < 8; p++) {
        int idx = tid + 256 * p;
        int kk = idx >> 4, seg = idx & 15;
        uint4 v = wsrc[kk * 32 + (n0g >> 3) + seg];
        *(uint4*)&Bs[kk * LDB + seg * 8] = v;
    }
    __syncthreads();

    int w    = tid >> 5;
    int lane = tid & 31;
    int wm = (w & 3) * 32;       // warp row offset
    int wn = (w >> 2) * 64;      // warp col offset

    float acc[2][8][4];
#pragma unroll
    for (int mt = 0; mt < 2; mt++)
#pragma unroll
        for (int nt = 0; nt < 8; nt++)
#pragma unroll
            for (int q = 0; q < 4; q++) acc[mt][nt][q] = 0.f;

#pragma unroll
    for (int ks = 0; ks < 8; ks++) {
        int k0 = ks * 16;
        unsigned afr[2][4];
#pragma unroll
        for (int mt = 0; mt < 2; mt++) {
            int r = wm + mt * 16 + (lane & 15);
            int c = k0 + (lane >> 4) * 8;
            unsigned addr = (unsigned)__cvta_generic_to_shared(&As[r * LDA + c]);
            asm volatile("ldmatrix.sync.aligned.m8n8.x4.shared.b16 {%0,%1,%2,%3}, [%4];"
                : "=r"(afr[mt][0]), "=r"(afr[mt][1]), "=r"(afr[mt][2]), "=r"(afr[mt][3])
                : "r"(addr));
        }
        unsigned bfr[8][2];
#pragma unroll
        for (int ntp = 0; ntp < 4; ntp++) {
            int kk = k0 + (lane & 15);
            int nn = wn + ntp * 16 + (lane >> 4) * 8;
            unsigned addr = (unsigned)__cvta_generic_to_shared(&Bs[kk * LDB + nn]);
            unsigned r0, r1, r2, r3;
            asm volatile("ldmatrix.sync.aligned.m8n8.x4.trans.shared.b16 {%0,%1,%2,%3}, [%4];"
                : "=r"(r0), "=r"(r1), "=r"(r2), "=r"(r3) : "r"(addr));
            bfr[ntp * 2][0] = r0;     bfr[ntp * 2][1] = r1;
            bfr[ntp * 2 + 1][0] = r2; bfr[ntp * 2 + 1][1] = r3;
        }
#pragma unroll
        for (int mt = 0; mt < 2; mt++)
#pragma unroll
            for (int nt = 0; nt < 8; nt++) {
                asm volatile(
                    "mma.sync.aligned.m16n8k16.row.col.f32.f16.f16.f32 "
                    "{%0,%1,%2,%3}, {%4,%5,%6,%7}, {%8,%9}, {%0,%1,%2,%3};"
                    : "+f"(acc[mt][nt][0]), "+f"(acc[mt][nt][1]),
                      "+f"(acc[mt][nt][2]), "+f"(acc[mt][nt][3])
                    : "r"(afr[mt][0]), "r"(afr[mt][1]), "r"(afr[mt][2]), "r"(afr[mt][3]),
                      "r"(bfr[nt][0]), "r"(bfr[nt][1]));
            }
    }

    // epilogue
    int g   = lane >> 2;
    int tig = lane & 3;
#pragma unroll
    for (int mt = 0; mt < 2; mt++) {
#pragma unroll
        for (int nt = 0; nt < 8; nt++) {
            int colg = n0g + wn + nt * 8 + tig * 2;
            float b0 = bias[colg], b1 = bias[colg + 1];
            int r0 = m0 + wm + mt * 16 + g;
            if (r0 < NN) {
                float2 v0 = make_float2(acc[mt][nt][0] + b0, acc[mt][nt][1] + b1);
                *(float2*)&out[r0 * DOUT + colg] = v0;
            }
            int r1 = r0 + 8;
            if (r1 < NN) {
                float2 v1 = make_float2(acc[mt][nt][2] + b0, acc[mt][nt][3] + b1);
                *(float2*)&out[r1 * DOUT + colg] = v1;
            }
        }
    }
}

// ---------------- launch ----------------
extern "C" void kernel_launch(void* const* d_in, const int* in_sizes, int n_in,
                              void* d_out, int out_size)
{
    const float* x    = (const float*)d_in[0];
    const int*   row  = (const int*)  d_in[1];
    const int*   col  = (const int*)  d_in[2];
    const float* adj  = (const float*)d_in[3];
    const float* Wr   = (const float*)d_in[4];
    const float* Wc   = (const float*)d_in[5];
    const float* Wx   = (const float*)d_in[6];
    const float* bx   = (const float*)d_in[7];
    float* out = (float*)d_out;

    const int GEMM_SMEM = (128 * LDA + 128 * LDB) * 2;   // 69632 B
    cudaFuncSetAttribute(gemm_kernel, cudaFuncAttributeMaxDynamicSharedMemorySize, GEMM_SMEM);

    zero_kernel<<<(NN + 255) / 256, 256>>>();
    wconv_kernel<<<(DIN * DOUT + 255) / 256, 256>>>(Wx);
    proj_kernel<<<(NN + PROJ_NODES - 1) / PROJ_NODES, 256>>>(x, Wr, Wc);
    hist_kernel<<<(EE + 255) / 256, 256>>>(row);
    scanA_kernel<<<NBLK, 1024>>>();
    scanB_kernel<<<1, 64>>>();
    scanC_kernel<<<NBLK, 1024>>>();
    edge_scatter_kernel<<<(EE + 255) / 256, 256>>>(row, col, adj);
    spmm_kernel<<<NN, 64>>>();
    gemm_kernel<<<dim3(DOUT / 128, (NN + 127) / 128), 256, GEMM_SMEM>>>(bx, out);
}

// round 6
// speedup vs baseline: 1.9937x; 1.0228x over previous
#include <cuda_runtime.h>
#include <cuda_fp16.h>
#include <cuda_bf16.h>

#define NN   50000
#define EE   1600000
#define DIN  128
#define DOUT 256
#define DA   32
#define NBLK ((NN + 1023) / 1024)   // 49

typedef unsigned long long ull;

// ---------------- device scratch (static, no allocations) ----------------
__device__ __half2 g_arowh[NN * 16];        // a_row as half2 (3.2 MB)
__device__ __half2 g_acolh[NN * 16];        // a_col as half2 (3.2 MB)
__device__ __half2 g_xh[NN * 64];           // x as half2     (12.8 MB)
__device__ __half2 g_hh[NN * 64];           // h as half2     (12.8 MB)
__device__ __half  g_Wh[DIN * DOUT];        // W_x as half    (64 KB)
__device__ float  g_deg[NN];
__device__ int    g_cnt [NN];
__device__ int    g_cnt2[NN];
__device__ int    g_off [NN + 1];
__device__ int    g_bsum[NBLK];
__device__ ull    g_edges8[EE];             // {lo: half2(ea,adj), hi: col*32} — 12.8 MB

// ---------------- kernel 0: zero counters + convert W ----------------
__global__ void init_kernel(const float* __restrict__ W) {
    int i = blockIdx.x * blockDim.x + threadIdx.x;
    if (i < NN) { g_cnt[i] = 0; g_cnt2[i] = 0; g_deg[i] = 0.f; }
    if (i < DIN * DOUT) g_Wh[i] = __float2half(W[i]);
}

// ---------------- kernel 1: projections + x->half2 convert ----------------
#define PROJ_NODES 16
__global__ __launch_bounds__(256) void proj_kernel(
    const float* __restrict__ x,
    const float* __restrict__ Wr,
    const float* __restrict__ Wc)
{
    __shared__ float Wsh[DIN][2 * DA];          // cols [0,32)=W_row, [32,64)=W_col
    __shared__ float xsh[PROJ_NODES][DIN + 1];
    int t = threadIdx.x;

    for (int i = t; i < DIN * DA; i += 256) {
        int k = i >> 5, j = i & 31;
        Wsh[k][j]      = Wr[i];
        Wsh[k][j + 32] = Wc[i];
    }
    int node0 = blockIdx.x * PROJ_NODES;
    for (int i = t; i < PROJ_NODES * DIN; i += 256) {
        int n = i >> 7, k = i & 127;
        int gn = node0 + n;
        xsh[n][k] = (gn < NN) ? x[gn * DIN + k] : 0.f;
    }
    __syncthreads();

    // write x as half2 (free conversion: x already staged in smem)
    for (int i = t; i < PROJ_NODES * 64; i += 256) {
        int n = i >> 6, k2 = i & 63;
        int gn = node0 + n;
        if (gn < NN)
            g_xh[gn * 64 + k2] = __floats2half2_rn(xsh[n][2 * k2], xsh[n][2 * k2 + 1]);
    }

    int n  = t & 15;       // local node
    int g  = t >> 4;       // output group 0..15 -> dims g*4..g*4+3
    int j0 = g * 4;
    float a0 = 0.f, a1 = 0.f, a2 = 0.f, a3 = 0.f;
#pragma unroll 8
    for (int k = 0; k < DIN; k++) {
        float xv = xsh[n][k];
        a0 += xv * Wsh[k][j0 + 0];
        a1 += xv * Wsh[k][j0 + 1];
        a2 += xv * Wsh[k][j0 + 2];
        a3 += xv * Wsh[k][j0 + 3];
    }
    int gn = node0 + n;
    if (gn < NN) {
        if (j0 < DA) {
            g_arowh[gn * 16 + (j0 >> 1)]     = __floats2half2_rn(a0, a1);
            g_arowh[gn * 16 + (j0 >> 1) + 1] = __floats2half2_rn(a2, a3);
        } else {
            int j = j0 - DA;
            g_acolh[gn * 16 + (j >> 1)]      = __floats2half2_rn(a0, a1);
            g_acolh[gn * 16 + (j >> 1) + 1]  = __floats2half2_rn(a2, a3);
        }
    }
}

// ---------------- kernel 2: degree histogram (4 edges/thread for MLP) ----------------
__global__ void hist_kernel(const int* __restrict__ row) {
    int i = blockIdx.x * blockDim.x + threadIdx.x;
    int e4 = i * 4;
    if (e4 < EE) {
        int4 r = *(const int4*)&row[e4];
        atomicAdd(&g_cnt[r.x], 1);
        atomicAdd(&g_cnt[r.y], 1);
        atomicAdd(&g_cnt[r.z], 1);
        atomicAdd(&g_cnt[r.w], 1);
    }
}

// ---------------- kernels 3a/3b/3c: two-level exclusive scan -> CSR offsets ----------------
__global__ __launch_bounds__(1024) void scanA_kernel() {
    __shared__ int wsum[32];
    int b = blockIdx.x, t = threadIdx.x;
    int i = b * 1024 + t;
    int lane = t & 31, w = t >> 5;
    int v = (i < NN) ? g_cnt[i] : 0;
    int s = v;
#pragma unroll
    for (int d = 1; d < 32; d <<= 1) {
        int n = __shfl_up_sync(0xffffffffu, s, d);
        if (lane >= d) s += n;
    }
    if (lane == 31) wsum[w] = s;
    __syncthreads();
    if (w == 0) {
        int ws = wsum[lane];
#pragma unroll
        for (int d = 1; d < 32; d <<= 1) {
            int n = __shfl_up_sync(0xffffffffu, ws, d);
            if (lane >= d) ws += n;
        }
        wsum[lane] = ws;
    }
    __syncthreads();
    int incl = s + (w > 0 ? wsum[w - 1] : 0);
    if (i < NN) g_off[i + 1] = incl;          // block-local inclusive
    if (t == 1023) g_bsum[b] = incl;          // block total
}

__global__ void scanB_kernel() {
    __shared__ int sh[64];
    int t = threadIdx.x;
    sh[t] = (t < NBLK) ? g_bsum[t] : 0;
    __syncthreads();
#pragma unroll
    for (int s = 1; s < 64; s <<= 1) {
        int a = (t >= s) ? sh[t - s] : 0;
        __syncthreads();
        sh[t] += a;
        __syncthreads();
    }
    if (t < NBLK) g_bsum[t] = sh[t];          // inclusive block prefix
}

__global__ __launch_bounds__(1024) void scanC_kernel() {
    int b = blockIdx.x, t = threadIdx.x;
    int i = b * 1024 + t;
    int add = (b > 0) ? g_bsum[b - 1] : 0;
    if (i < NN) g_off[i + 1] += add;
    if (b == 0 && t == 0) g_off[0] = 0;
}

// ---------------- kernel 4: per-edge attention + scatter into CSR order ----------------
__global__ __launch_bounds__(256) void edge_scatter_kernel(
    const int*   __restrict__ row,
    const int*   __restrict__ col,
    const float* __restrict__ adj)
{
    int e = blockIdx.x * blockDim.x + threadIdx.x;
    if (e >= EE) return;
    int r = row[e], c = col[e];
    const uint4* ar4 = (const uint4*)&g_arowh[r * 16];
    const uint4* ac4 = (const uint4*)&g_acolh[c * 16];
    float dot = 0.f;
#pragma unroll
    for (int q = 0; q < 4; q++) {              // 4 x uint4 = 64 B = all 32 dims
        uint4 A = ar4[q], B = ac4[q];
        const __half2* ah = (const __half2*)&A;
        const __half2* bh = (const __half2*)&B;
#pragma unroll
        for (int j = 0; j < 4; j++) {
            float2 a = __half22float2(ah[j]);
            float2 b = __half22float2(bh[j]);
            dot += a.x * b.x + a.y * b.y;
        }
    }
    float s = dot * 0.17677669529663687f;      // rsqrt(32)
    if (s < 0.f) s *= 0.2f;                    // leaky relu
    float ea = __expf(s);
    atomicAdd(&g_deg[r], ea);
    int pos = g_off[r] + atomicAdd(&g_cnt2[r], 1);
    __half2 p2 = __floats2half2_rn(ea, adj[e]);
    unsigned lo = *reinterpret_cast<unsigned*>(&p2);
    g_edges8[pos] = (ull)lo | ((ull)(unsigned)(c * 32) << 32);   // col as uint2 index
}

// ---------------- kernel 5: warp-per-node gather SpMM (half2 x) -> h fp16 ----------------
__global__ __launch_bounds__(128) void spmm_kernel() {
    int w = threadIdx.x >> 5, lane = threadIdx.x & 31;
    int i = blockIdx.x * 4 + w;
    if (i >= NN) return;
    int start = g_off[i], end = g_off[i + 1];
    float inv = 1.f / (g_deg[i] + 1e-15f);
    const uint2* x2 = (const uint2*)g_xh;      // one uint2 = 4 dims; row = 32 uint2

    float a0 = 0.f, a1 = 0.f, a2 = 0.f, a3 = 0.f;
    for (int base = start; base < end; base += 32) {
        int k = base + lane;
        float myval = 0.f;
        int   mycol = 0;
        if (k < end) {
            ull p = g_edges8[k];
            unsigned lo = (unsigned)p;
            __half2 h2 = *reinterpret_cast<__half2*>(&lo);
            float2 f = __half22float2(h2);               // {ea, adj}
            myval = (f.y + f.x * inv) * 0.5f;
            mycol = (int)(p >> 32);
        }
        int m = min(32, end - base);
        for (int j = 0; j < m; j++) {
            float v  = __shfl_sync(0xffffffffu, myval, j);
            int   cb = __shfl_sync(0xffffffffu, mycol, j);
            uint2 xv = x2[cb + lane];
            __half2 xa = *reinterpret_cast<__half2*>(&xv.x);
            __half2 xb = *reinterpret_cast<__half2*>(&xv.y);
            float2 fa = __half22float2(xa);
            float2 fb = __half22float2(xb);
            a0 += v * fa.x; a1 += v * fa.y;
            a2 += v * fb.x; a3 += v * fb.y;
        }
    }
    uint2 o;
    __half2 o0 = __floats2half2_rn(a0, a1);
    __half2 o1 = __floats2half2_rn(a2, a3);
    o.x = *reinterpret_cast<unsigned*>(&o0);
    o.y = *reinterpret_cast<unsigned*>(&o1);
    *(uint2*)&g_hh[i * 64 + lane * 2] = o;
}

// ---------------- kernel 6: out = h @ W_x + b_x (HMMA m16n8k16) ----------------
// BM=128, BN=128, single K=128 pass. 256 threads (8 warps), warp tile 32x64.
#define LDA 136
#define LDB 136
__global__ __launch_bounds__(256) void gemm_kernel(
    const float* __restrict__ bias,
    float* __restrict__ out)
{
    extern __shared__ __half sm[];
    __half* As = sm;                 // [128][LDA]
    __half* Bs = sm + 128 * LDA;     // [128][LDB]

    int tid = threadIdx.x;
    int m0  = blockIdx.y * 128;
    int n0g = blockIdx.x * 128;

    // load A: h rows m0..m0+127 (256 B each = 16 uint4)
    const uint4* hsrc = (const uint4*)g_hh;
#pragma unroll
    for (int p = 0; p < 8; p++) {
        int idx = tid + 256 * p;
        int r = idx >> 4, seg = idx & 15;
        uint4 v = make_uint4(0u, 0u, 0u, 0u);
        if (m0 + r < NN) v = hsrc[(m0 + r) * 16 + seg];
        *(uint4*)&As[r * LDA + seg * 8] = v;
    }
    // load B: W rows k=0..127, cols n0g..n0g+127 (16 uint4 per row slice)
    const uint4* wsrc = (const uint4*)g_Wh;
#pragma unroll
    for (int p = 0; p < 8; p++) {
        int idx = tid + 256 * p;
        int kk = idx >> 4, seg = idx & 15;
        uint4 v = wsrc[kk * 32 + (n0g >> 3) + seg];
        *(uint4*)&Bs[kk * LDB + seg * 8] = v;
    }
    __syncthreads();

    int w    = tid >> 5;
    int lane = tid & 31;
    int wm = (w & 3) * 32;       // warp row offset
    int wn = (w >> 2) * 64;      // warp col offset

    float acc[2][8][4];
#pragma unroll
    for (int mt = 0; mt < 2; mt++)
#pragma unroll
        for (int nt = 0; nt < 8; nt++)
#pragma unroll
            for (int q = 0; q < 4; q++) acc[mt][nt][q] = 0.f;

#pragma unroll
    for (int ks = 0; ks < 8; ks++) {
        int k0 = ks * 16;
        unsigned afr[2][4];
#pragma unroll
        for (int mt = 0; mt < 2; mt++) {
            int r = wm + mt * 16 + (lane & 15);
            int c = k0 + (lane >> 4) * 8;
            unsigned addr = (unsigned)__cvta_generic_to_shared(&As[r * LDA + c]);
            asm volatile("ldmatrix.sync.aligned.m8n8.x4.shared.b16 {%0,%1,%2,%3}, [%4];"
                : "=r"(afr[mt][0]), "=r"(afr[mt][1]), "=r"(afr[mt][2]), "=r"(afr[mt][3])
                : "r"(addr));
        }
        unsigned bfr[8][2];
#pragma unroll
        for (int ntp = 0; ntp < 4; ntp++) {
            int kk = k0 + (lane & 15);
            int nn = wn + ntp * 16 + (lane >> 4) * 8;
            unsigned addr = (unsigned)__cvta_generic_to_shared(&Bs[kk * LDB + nn]);
            unsigned r0, r1, r2, r3;
            asm volatile("ldmatrix.sync.aligned.m8n8.x4.trans.shared.b16 {%0,%1,%2,%3}, [%4];"
                : "=r"(r0), "=r"(r1), "=r"(r2), "=r"(r3) : "r"(addr));
            bfr[ntp * 2][0] = r0;     bfr[ntp * 2][1] = r1;
            bfr[ntp * 2 + 1][0] = r2; bfr[ntp * 2 + 1][1] = r3;
        }
#pragma unroll
        for (int mt = 0; mt < 2; mt++)
#pragma unroll
            for (int nt = 0; nt < 8; nt++) {
                asm volatile(
                    "mma.sync.aligned.m16n8k16.row.col.f32.f16.f16.f32 "
                    "{%0,%1,%2,%3}, {%4,%5,%6,%7}, {%8,%9}, {%0,%1,%2,%3};"
                    : "+f"(acc[mt][nt][0]), "+f"(acc[mt][nt][1]),
                      "+f"(acc[mt][nt][2]), "+f"(acc[mt][nt][3])
                    : "r"(afr[mt][0]), "r"(afr[mt][1]), "r"(afr[mt][2]), "r"(afr[mt][3]),
                      "r"(bfr[nt][0]), "r"(bfr[nt][1]));
            }
    }

    // epilogue
    int g   = lane >> 2;
    int tig = lane & 3;
#pragma unroll
    for (int mt = 0; mt < 2; mt++) {
#pragma unroll
        for (int nt = 0; nt < 8; nt++) {
            int colg = n0g + wn + nt * 8 + tig * 2;
            float b0 = bias[colg], b1 = bias[colg + 1];
            int r0 = m0 + wm + mt * 16 + g;
            if (r0 < NN) {
                float2 v0 = make_float2(acc[mt][nt][0] + b0, acc[mt][nt][1] + b1);
                *(float2*)&out[r0 * DOUT + colg] = v0;
            }
            int r1 = r0 + 8;
            if (r1 < NN) {
                float2 v1 = make_float2(acc[mt][nt][2] + b0, acc[mt][nt][3] + b1);
                *(float2*)&out[r1 * DOUT + colg] = v1;
            }
        }
    }
}

// ---------------- launch ----------------
extern "C" void kernel_launch(void* const* d_in, const int* in_sizes, int n_in,
                              void* d_out, int out_size)
{
    const float* x    = (const float*)d_in[0];
    const int*   row  = (const int*)  d_in[1];
    const int*   col  = (const int*)  d_in[2];
    const float* adj  = (const float*)d_in[3];
    const float* Wr   = (const float*)d_in[4];
    const float* Wc   = (const float*)d_in[5];
    const float* Wx   = (const float*)d_in[6];
    const float* bx   = (const float*)d_in[7];
    float* out = (float*)d_out;

    const int GEMM_SMEM = (128 * LDA + 128 * LDB) * 2;   // 69632 B
    cudaFuncSetAttribute(gemm_kernel, cudaFuncAttributeMaxDynamicSharedMemorySize, GEMM_SMEM);

    init_kernel<<<(NN + 255) / 256, 256>>>(Wx);
    proj_kernel<<<(NN + PROJ_NODES - 1) / PROJ_NODES, 256>>>(x, Wr, Wc);
    hist_kernel<<<(EE / 4 + 255) / 256, 256>>>(row);
    scanA_kernel<<<NBLK, 1024>>>();
    scanB_kernel<<<1, 64>>>();
    scanC_kernel<<<NBLK, 1024>>>();
    edge_scatter_kernel<<<(EE + 255) / 256, 256>>>(row, col, adj);
    spmm_kernel<<<(NN + 3) / 4, 128>>>();
    gemm_kernel<<<dim3(DOUT / 128, (NN + 127) / 128), 256, GEMM_SMEM>>>(bx, out);
}

// round 7
// speedup vs baseline: 2.1150x; 1.0608x over previous
#include <cuda_runtime.h>
#include <cuda_fp16.h>
#include <cuda_bf16.h>

#define NN   50000
#define EE   1600000
#define DIN  128
#define DOUT 256
#define DA   32
#define NBLK ((NN + 1023) / 1024)   // 49

typedef unsigned long long ull;

// ---------------- device scratch (static, no allocations) ----------------
__device__ __half2 g_arowh[NN * 16];        // a_row as half2 (3.2 MB)
__device__ __half2 g_acolh[NN * 16];        // a_col as half2 (3.2 MB)
__device__ __half2 g_xh[NN * 64];           // x as half2     (12.8 MB)
__device__ __half2 g_hh[NN * 64];           // h as half2     (12.8 MB)
__device__ __half  g_Wh[DIN * DOUT];        // W_x as half    (64 KB)
__device__ float  g_deg[NN];
__device__ int    g_cnt [NN];
__device__ int    g_cnt2[NN];
__device__ int    g_off [NN + 1];
__device__ int    g_bsum[NBLK];
__device__ ull    g_edges8[EE];             // {lo: half2(ea,adj), hi: col*32} — 12.8 MB

// ---------------- kernel 0: zero counters + convert W ----------------
__global__ void init_kernel(const float* __restrict__ W) {
    int i = blockIdx.x * blockDim.x + threadIdx.x;
    if (i < NN) { g_cnt[i] = 0; g_cnt2[i] = 0; g_deg[i] = 0.f; }
    if (i < DIN * DOUT) g_Wh[i] = __float2half(W[i]);
}

// ---------------- kernel 1: projections + x->half2 convert ----------------
#define PROJ_NODES 16
__global__ __launch_bounds__(256) void proj_kernel(
    const float* __restrict__ x,
    const float* __restrict__ Wr,
    const float* __restrict__ Wc)
{
    __shared__ float Wsh[DIN][2 * DA];          // cols [0,32)=W_row, [32,64)=W_col
    __shared__ float xsh[PROJ_NODES][DIN + 1];
    int t = threadIdx.x;

    for (int i = t; i < DIN * DA; i += 256) {
        int k = i >> 5, j = i & 31;
        Wsh[k][j]      = Wr[i];
        Wsh[k][j + 32] = Wc[i];
    }
    int node0 = blockIdx.x * PROJ_NODES;
    for (int i = t; i < PROJ_NODES * DIN; i += 256) {
        int n = i >> 7, k = i & 127;
        int gn = node0 + n;
        xsh[n][k] = (gn < NN) ? x[gn * DIN + k] : 0.f;
    }
    __syncthreads();

    // write x as half2 (free conversion: x already staged in smem)
    for (int i = t; i < PROJ_NODES * 64; i += 256) {
        int n = i >> 6, k2 = i & 63;
        int gn = node0 + n;
        if (gn < NN)
            g_xh[gn * 64 + k2] = __floats2half2_rn(xsh[n][2 * k2], xsh[n][2 * k2 + 1]);
    }

    int n  = t & 15;       // local node
    int g  = t >> 4;       // output group 0..15 -> dims g*4..g*4+3
    int j0 = g * 4;
    float a0 = 0.f, a1 = 0.f, a2 = 0.f, a3 = 0.f;
#pragma unroll 8
    for (int k = 0; k < DIN; k++) {
        float xv = xsh[n][k];
        a0 += xv * Wsh[k][j0 + 0];
        a1 += xv * Wsh[k][j0 + 1];
        a2 += xv * Wsh[k][j0 + 2];
        a3 += xv * Wsh[k][j0 + 3];
    }
    int gn = node0 + n;
    if (gn < NN) {
        if (j0 < DA) {
            g_arowh[gn * 16 + (j0 >> 1)]     = __floats2half2_rn(a0, a1);
            g_arowh[gn * 16 + (j0 >> 1) + 1] = __floats2half2_rn(a2, a3);
        } else {
            int j = j0 - DA;
            g_acolh[gn * 16 + (j >> 1)]      = __floats2half2_rn(a0, a1);
            g_acolh[gn * 16 + (j >> 1) + 1]  = __floats2half2_rn(a2, a3);
        }
    }
}

// ---------------- kernel 2: degree histogram (4 edges/thread for MLP) ----------------
__global__ void hist_kernel(const int* __restrict__ row) {
    int i = blockIdx.x * blockDim.x + threadIdx.x;
    int e4 = i * 4;
    if (e4 < EE) {
        int4 r = *(const int4*)&row[e4];
        atomicAdd(&g_cnt[r.x], 1);
        atomicAdd(&g_cnt[r.y], 1);
        atomicAdd(&g_cnt[r.z], 1);
        atomicAdd(&g_cnt[r.w], 1);
    }
}

// ---------------- kernels 3a/3b/3c: two-level exclusive scan -> CSR offsets ----------------
__global__ __launch_bounds__(1024) void scanA_kernel() {
    __shared__ int wsum[32];
    int b = blockIdx.x, t = threadIdx.x;
    int i = b * 1024 + t;
    int lane = t & 31, w = t >> 5;
    int v = (i < NN) ? g_cnt[i] : 0;
    int s = v;
#pragma unroll
    for (int d = 1; d < 32; d <<= 1) {
        int n = __shfl_up_sync(0xffffffffu, s, d);
        if (lane >= d) s += n;
    }
    if (lane == 31) wsum[w] = s;
    __syncthreads();
    if (w == 0) {
        int ws = wsum[lane];
#pragma unroll
        for (int d = 1; d < 32; d <<= 1) {
            int n = __shfl_up_sync(0xffffffffu, ws, d);
            if (lane >= d) ws += n;
        }
        wsum[lane] = ws;
    }
    __syncthreads();
    int incl = s + (w > 0 ? wsum[w - 1] : 0);
    if (i < NN) g_off[i + 1] = incl;          // block-local inclusive
    if (t == 1023) g_bsum[b] = incl;          // block total
}

__global__ void scanB_kernel() {
    __shared__ int sh[64];
    int t = threadIdx.x;
    sh[t] = (t < NBLK) ? g_bsum[t] : 0;
    __syncthreads();
#pragma unroll
    for (int s = 1; s < 64; s <<= 1) {
        int a = (t >= s) ? sh[t - s] : 0;
        __syncthreads();
        sh[t] += a;
        __syncthreads();
    }
    if (t < NBLK) g_bsum[t] = sh[t];          // inclusive block prefix
}

__global__ __launch_bounds__(1024) void scanC_kernel() {
    int b = blockIdx.x, t = threadIdx.x;
    int i = b * 1024 + t;
    int add = (b > 0) ? g_bsum[b - 1] : 0;
    if (i < NN) g_off[i + 1] += add;
    if (b == 0 && t == 0) g_off[0] = 0;
}

// ---------------- kernel 4: per-edge attention + scatter into CSR order ----------------
__global__ __launch_bounds__(256) void edge_scatter_kernel(
    const int*   __restrict__ row,
    const int*   __restrict__ col,
    const float* __restrict__ adj)
{
    int e = blockIdx.x * blockDim.x + threadIdx.x;
    if (e >= EE) return;
    int r = row[e], c = col[e];
    const uint4* ar4 = (const uint4*)&g_arowh[r * 16];
    const uint4* ac4 = (const uint4*)&g_acolh[c * 16];
    float dot = 0.f;
#pragma unroll
    for (int q = 0; q < 4; q++) {              // 4 x uint4 = 64 B = all 32 dims
        uint4 A = ar4[q], B = ac4[q];
        const __half2* ah = (const __half2*)&A;
        const __half2* bh = (const __half2*)&B;
#pragma unroll
        for (int j = 0; j < 4; j++) {
            float2 a = __half22float2(ah[j]);
            float2 b = __half22float2(bh[j]);
            dot += a.x * b.x + a.y * b.y;
        }
    }
    float s = dot * 0.17677669529663687f;      // rsqrt(32)
    if (s < 0.f) s *= 0.2f;                    // leaky relu
    float ea = __expf(s);
    atomicAdd(&g_deg[r], ea);
    int pos = g_off[r] + atomicAdd(&g_cnt2[r], 1);
    __half2 p2 = __floats2half2_rn(ea, adj[e]);
    unsigned lo = *reinterpret_cast<unsigned*>(&p2);
    g_edges8[pos] = (ull)lo | ((ull)(unsigned)(c * 32) << 32);   // col as uint2 index
}

// ---------------- kernel 5: warp-per-node gather SpMM (half2 x) -> h fp16 ----------------
__global__ __launch_bounds__(128) void spmm_kernel() {
    int w = threadIdx.x >> 5, lane = threadIdx.x & 31;
    int i = blockIdx.x * 4 + w;
    if (i >= NN) return;
    int start = g_off[i], end = g_off[i + 1];
    float inv = 1.f / (g_deg[i] + 1e-15f);
    const uint2* x2 = (const uint2*)g_xh;      // one uint2 = 4 dims; row = 32 uint2

    float a0 = 0.f, a1 = 0.f, a2 = 0.f, a3 = 0.f;
    int base = start;

    // full 32-edge chunks: fixed bound + unroll -> batched independent LDGs
    for (; base + 32 <= end; base += 32) {
        ull p = g_edges8[base + lane];
        unsigned lo = (unsigned)p;
        __half2 h2 = *reinterpret_cast<__half2*>(&lo);
        float2 f = __half22float2(h2);               // {ea, adj}
        float myval = (f.y + f.x * inv) * 0.5f;
        int   mycol = (int)(p >> 32);
#pragma unroll 8
        for (int j = 0; j < 32; j++) {
            float v  = __shfl_sync(0xffffffffu, myval, j);
            int   cb = __shfl_sync(0xffffffffu, mycol, j);
            uint2 xv = x2[cb + lane];
            __half2 xa = *reinterpret_cast<__half2*>(&xv.x);
            __half2 xb = *reinterpret_cast<__half2*>(&xv.y);
            float2 fa = __half22float2(xa);
            float2 fb = __half22float2(xb);
            a0 += v * fa.x; a1 += v * fa.y;
            a2 += v * fb.x; a3 += v * fb.y;
        }
    }
    // tail
    if (base < end) {
        int k = base + lane;
        float myval = 0.f;
        int   mycol = 0;
        if (k < end) {
            ull p = g_edges8[k];
            unsigned lo = (unsigned)p;
            __half2 h2 = *reinterpret_cast<__half2*>(&lo);
            float2 f = __half22float2(h2);
            myval = (f.y + f.x * inv) * 0.5f;
            mycol = (int)(p >> 32);
        }
        int m = end - base;
        for (int j = 0; j < m; j++) {
            float v  = __shfl_sync(0xffffffffu, myval, j);
            int   cb = __shfl_sync(0xffffffffu, mycol, j);
            uint2 xv = x2[cb + lane];
            __half2 xa = *reinterpret_cast<__half2*>(&xv.x);
            __half2 xb = *reinterpret_cast<__half2*>(&xv.y);
            float2 fa = __half22float2(xa);
            float2 fb = __half22float2(xb);
            a0 += v * fa.x; a1 += v * fa.y;
            a2 += v * fb.x; a3 += v * fb.y;
        }
    }

    uint2 o;
    __half2 o0 = __floats2half2_rn(a0, a1);
    __half2 o1 = __floats2half2_rn(a2, a3);
    o.x = *reinterpret_cast<unsigned*>(&o0);
    o.y = *reinterpret_cast<unsigned*>(&o1);
    *(uint2*)&g_hh[i * 64 + lane * 2] = o;
}

// ---------------- kernel 6: out = h @ W_x + b_x (HMMA m16n8k16) ----------------
// BM=128, BN=128, single K=128 pass. 256 threads (8 warps), warp tile 32x64.
#define LDA 136
#define LDB 136
__global__ __launch_bounds__(256) void gemm_kernel(
    const float* __restrict__ bias,
    float* __restrict__ out)
{
    extern __shared__ __half sm[];
    __half* As = sm;                 // [128][LDA]
    __half* Bs = sm + 128 * LDA;     // [128][LDB]

    int tid = threadIdx.x;
    int m0  = blockIdx.y * 128;
    int n0g = blockIdx.x * 128;

    // load A: h rows m0..m0+127 (256 B each = 16 uint4)
    const uint4* hsrc = (const uint4*)g_hh;
#pragma unroll
    for (int p = 0; p < 8; p++) {
        int idx = tid + 256 * p;
        int r = idx >> 4, seg = idx & 15;
        uint4 v = make_uint4(0u, 0u, 0u, 0u);
        if (m0 + r < NN) v = hsrc[(m0 + r) * 16 + seg];
        *(uint4*)&As[r * LDA + seg * 8] = v;
    }
    // load B: W rows k=0..127, cols n0g..n0g+127 (16 uint4 per row slice)
    const uint4* wsrc = (const uint4*)g_Wh;
#pragma unroll
    for (int p = 0; p < 8; p++) {
        int idx = tid + 256 * p;
        int kk = idx >> 4, seg = idx & 15;
        uint4 v = wsrc[kk * 32 + (n0g >> 3) + seg];
        *(uint4*)&Bs[kk * LDB + seg * 8] = v;
    }
    __syncthreads();

    int w    = tid >> 5;
    int lane = tid & 31;
    int wm = (w & 3) * 32;       // warp row offset
    int wn = (w >> 2) * 64;      // warp col offset

    float acc[2][8][4];
#pragma unroll
    for (int mt = 0; mt < 2; mt++)
#pragma unroll
        for (int nt = 0; nt < 8; nt++)
#pragma unroll
            for (int q = 0; q < 4; q++) acc[mt][nt][q] = 0.f;

#pragma unroll
    for (int ks = 0; ks < 8; ks++) {
        int k0 = ks * 16;
        unsigned afr[2][4];
#pragma unroll
        for (int mt = 0; mt < 2; mt++) {
            int r = wm + mt * 16 + (lane & 15);
            int c = k0 + (lane >> 4) * 8;
            unsigned addr = (unsigned)__cvta_generic_to_shared(&As[r * LDA + c]);
            asm volatile("ldmatrix.sync.aligned.m8n8.x4.shared.b16 {%0,%1,%2,%3}, [%4];"
                : "=r"(afr[mt][0]), "=r"(afr[mt][1]), "=r"(afr[mt][2]), "=r"(afr[mt][3])
                : "r"(addr));
        }
        unsigned bfr[8][2];
#pragma unroll
        for (int ntp = 0; ntp < 4; ntp++) {
            int kk = k0 + (lane & 15);
            int nn = wn + ntp * 16 + (lane >> 4) * 8;
            unsigned addr = (unsigned)__cvta_generic_to_shared(&Bs[kk * LDB + nn]);
            unsigned r0, r1, r2, r3;
            asm volatile("ldmatrix.sync.aligned.m8n8.x4.trans.shared.b16 {%0,%1,%2,%3}, [%4];"
                : "=r"(r0), "=r"(r1), "=r"(r2), "=r"(r3) : "r"(addr));
            bfr[ntp * 2][0] = r0;     bfr[ntp * 2][1] = r1;
            bfr[ntp * 2 + 1][0] = r2; bfr[ntp * 2 + 1][1] = r3;
        }
#pragma unroll
        for (int mt = 0; mt < 2; mt++)
#pragma unroll
            for (int nt = 0; nt < 8; nt++) {
                asm volatile(
                    "mma.sync.aligned.m16n8k16.row.col.f32.f16.f16.f32 "
                    "{%0,%1,%2,%3}, {%4,%5,%6,%7}, {%8,%9}, {%0,%1,%2,%3};"
                    : "+f"(acc[mt][nt][0]), "+f"(acc[mt][nt][1]),
                      "+f"(acc[mt][nt][2]), "+f"(acc[mt][nt][3])
                    : "r"(afr[mt][0]), "r"(afr[mt][1]), "r"(afr[mt][2]), "r"(afr[mt][3]),
                      "r"(bfr[nt][0]), "r"(bfr[nt][1]));
            }
    }

    // epilogue
    int g   = lane >> 2;
    int tig = lane & 3;
#pragma unroll
    for (int mt = 0; mt < 2; mt++) {
#pragma unroll
        for (int nt = 0; nt < 8; nt++) {
            int colg = n0g + wn + nt * 8 + tig * 2;
            float b0 = bias[colg], b1 = bias[colg + 1];
            int r0 = m0 + wm + mt * 16 + g;
            if (r0 < NN) {
                float2 v0 = make_float2(acc[mt][nt][0] + b0, acc[mt][nt][1] + b1);
                *(float2*)&out[r0 * DOUT + colg] = v0;
            }
            int r1 = r0 + 8;
            if (r1 < NN) {
                float2 v1 = make_float2(acc[mt][nt][2] + b0, acc[mt][nt][3] + b1);
                *(float2*)&out[r1 * DOUT + colg] = v1;
            }
        }
    }
}

// ---------------- launch ----------------
extern "C" void kernel_launch(void* const* d_in, const int* in_sizes, int n_in,
                              void* d_out, int out_size)
{
    const float* x    = (const float*)d_in[0];
    const int*   row  = (const int*)  d_in[1];
    const int*   col  = (const int*)  d_in[2];
    const float* adj  = (const float*)d_in[3];
    const float* Wr   = (const float*)d_in[4];
    const float* Wc   = (const float*)d_in[5];
    const float* Wx   = (const float*)d_in[6];
    const float* bx   = (const float*)d_in[7];
    float* out = (float*)d_out;

    // one-time resources (no device memory; identical captured work every call)
    static cudaStream_t s1 = nullptr;
    static cudaEvent_t evFork = nullptr, evJoin = nullptr;
    static bool smem_set = false;
    const int GEMM_SMEM = (128 * LDA + 128 * LDB) * 2;   // 69632 B
    if (!s1) {
        cudaStreamCreateWithFlags(&s1, cudaStreamNonBlocking);
        cudaEventCreateWithFlags(&evFork, cudaEventDisableTiming);
        cudaEventCreateWithFlags(&evJoin, cudaEventDisableTiming);
    }
    if (!smem_set) {
        cudaFuncSetAttribute(gemm_kernel, cudaFuncAttributeMaxDynamicSharedMemorySize, GEMM_SMEM);
        smem_set = true;
    }

    // fork: proj on s1 runs concurrently with init+hist+scan chain on stream 0
    cudaEventRecord(evFork, 0);
    cudaStreamWaitEvent(s1, evFork, 0);
    proj_kernel<<<(NN + PROJ_NODES - 1) / PROJ_NODES, 256, 0, s1>>>(x, Wr, Wc);
    cudaEventRecord(evJoin, s1);

    init_kernel<<<(NN + 255) / 256, 256>>>(Wx);
    hist_kernel<<<(EE / 4 + 255) / 256, 256>>>(row);
    scanA_kernel<<<NBLK, 1024>>>();
    scanB_kernel<<<1, 64>>>();
    scanC_kernel<<<NBLK, 1024>>>();

    // join: edge_scatter needs proj outputs + scan outputs
    cudaStreamWaitEvent(0, evJoin, 0);
    edge_scatter_kernel<<<(EE + 255) / 256, 256>>>(row, col, adj);
    spmm_kernel<<<(NN + 3) / 4, 128>>>();
    gemm_kernel<<<dim3(DOUT / 128, (NN + 127) / 128), 256, GEMM_SMEM>>>(bx, out);
}

// round 8
// speedup vs baseline: 2.2139x; 1.0468x over previous
#include <cuda_runtime.h>
#include <cuda_fp16.h>
#include <cuda_bf16.h>

#define NN   50000
#define EE   1600000
#define DIN  128
#define DOUT 256
#define DA   32
#define NBLK ((NN + 1023) / 1024)   // 49

typedef unsigned long long ull;

// ---------------- device scratch (static, no allocations) ----------------
__device__ __half2 g_arowh[NN * 16];        // a_row as half2 (3.2 MB)
__device__ __half2 g_acolh[NN * 16];        // a_col as half2 (3.2 MB)
__device__ __half2 g_xh[NN * 64];           // x as half2     (12.8 MB)
__device__ __half2 g_hh[NN * 64];           // h as half2     (12.8 MB)
__device__ __half  g_Wh[DIN * DOUT];        // W_x as half    (64 KB)
__device__ int    g_cnt [NN];
__device__ int    g_cnt2[NN];
__device__ int    g_off [NN + 1];
__device__ int    g_bsum[NBLK];
__device__ uint2  g_ecol[EE];               // {col*32, adj fp32 bits} CSR order — 12.8 MB
__device__ float  g_ea[EE];                 // exp(atten) CSR order — 6.4 MB

// ---------------- kernel 0: zero counters + convert W ----------------
__global__ void init_kernel(const float* __restrict__ W) {
    int i = blockIdx.x * blockDim.x + threadIdx.x;
    if (i < NN) { g_cnt[i] = 0; g_cnt2[i] = 0; }
    if (i < DIN * DOUT) g_Wh[i] = __float2half(W[i]);
}

// ---------------- kernel 1: projections + x->half2 convert ----------------
#define PROJ_NODES 16
__global__ __launch_bounds__(256) void proj_kernel(
    const float* __restrict__ x,
    const float* __restrict__ Wr,
    const float* __restrict__ Wc)
{
    __shared__ float Wsh[DIN][2 * DA];          // cols [0,32)=W_row, [32,64)=W_col
    __shared__ float xsh[PROJ_NODES][DIN + 1];
    int t = threadIdx.x;

    for (int i = t; i < DIN * DA; i += 256) {
        int k = i >> 5, j = i & 31;
        Wsh[k][j]      = Wr[i];
        Wsh[k][j + 32] = Wc[i];
    }
    int node0 = blockIdx.x * PROJ_NODES;
    for (int i = t; i < PROJ_NODES * DIN; i += 256) {
        int n = i >> 7, k = i & 127;
        int gn = node0 + n;
        xsh[n][k] = (gn < NN) ? x[gn * DIN + k] : 0.f;
    }
    __syncthreads();

    // write x as half2 (free conversion: x already staged in smem)
    for (int i = t; i < PROJ_NODES * 64; i += 256) {
        int n = i >> 6, k2 = i & 63;
        int gn = node0 + n;
        if (gn < NN)
            g_xh[gn * 64 + k2] = __floats2half2_rn(xsh[n][2 * k2], xsh[n][2 * k2 + 1]);
    }

    int n  = t & 15;       // local node
    int g  = t >> 4;       // output group 0..15 -> dims g*4..g*4+3
    int j0 = g * 4;
    float a0 = 0.f, a1 = 0.f, a2 = 0.f, a3 = 0.f;
#pragma unroll 8
    for (int k = 0; k < DIN; k++) {
        float xv = xsh[n][k];
        a0 += xv * Wsh[k][j0 + 0];
        a1 += xv * Wsh[k][j0 + 1];
        a2 += xv * Wsh[k][j0 + 2];
        a3 += xv * Wsh[k][j0 + 3];
    }
    int gn = node0 + n;
    if (gn < NN) {
        if (j0 < DA) {
            g_arowh[gn * 16 + (j0 >> 1)]     = __floats2half2_rn(a0, a1);
            g_arowh[gn * 16 + (j0 >> 1) + 1] = __floats2half2_rn(a2, a3);
        } else {
            int j = j0 - DA;
            g_acolh[gn * 16 + (j >> 1)]      = __floats2half2_rn(a0, a1);
            g_acolh[gn * 16 + (j >> 1) + 1]  = __floats2half2_rn(a2, a3);
        }
    }
}

// ---------------- kernel 2: degree histogram (4 edges/thread for MLP) ----------------
__global__ void hist_kernel(const int* __restrict__ row) {
    int i = blockIdx.x * blockDim.x + threadIdx.x;
    int e4 = i * 4;
    if (e4 < EE) {
        int4 r = *(const int4*)&row[e4];
        atomicAdd(&g_cnt[r.x], 1);
        atomicAdd(&g_cnt[r.y], 1);
        atomicAdd(&g_cnt[r.z], 1);
        atomicAdd(&g_cnt[r.w], 1);
    }
}

// ---------------- kernels 3a/3b/3c: two-level exclusive scan -> CSR offsets ----------------
__global__ __launch_bounds__(1024) void scanA_kernel() {
    __shared__ int wsum[32];
    int b = blockIdx.x, t = threadIdx.x;
    int i = b * 1024 + t;
    int lane = t & 31, w = t >> 5;
    int v = (i < NN) ? g_cnt[i] : 0;
    int s = v;
#pragma unroll
    for (int d = 1; d < 32; d <<= 1) {
        int n = __shfl_up_sync(0xffffffffu, s, d);
        if (lane >= d) s += n;
    }
    if (lane == 31) wsum[w] = s;
    __syncthreads();
    if (w == 0) {
        int ws = wsum[lane];
#pragma unroll
        for (int d = 1; d < 32; d <<= 1) {
            int n = __shfl_up_sync(0xffffffffu, ws, d);
            if (lane >= d) ws += n;
        }
        wsum[lane] = ws;
    }
    __syncthreads();
    int incl = s + (w > 0 ? wsum[w - 1] : 0);
    if (i < NN) g_off[i + 1] = incl;          // block-local inclusive
    if (t == 1023) g_bsum[b] = incl;          // block total
}

__global__ void scanB_kernel() {
    __shared__ int sh[64];
    int t = threadIdx.x;
    sh[t] = (t < NBLK) ? g_bsum[t] : 0;
    __syncthreads();
#pragma unroll
    for (int s = 1; s < 64; s <<= 1) {
        int a = (t >= s) ? sh[t - s] : 0;
        __syncthreads();
        sh[t] += a;
        __syncthreads();
    }
    if (t < NBLK) g_bsum[t] = sh[t];          // inclusive block prefix
}

__global__ __launch_bounds__(1024) void scanC_kernel() {
    int b = blockIdx.x, t = threadIdx.x;
    int i = b * 1024 + t;
    int add = (b > 0) ? g_bsum[b - 1] : 0;
    if (i < NN) g_off[i + 1] += add;
    if (b == 0 && t == 0) g_off[0] = 0;
}

// ---------------- kernel 4: minimal CSR scatter of {col, adj} (2 edges/thread) ----------------
__global__ __launch_bounds__(256) void scatter_kernel(
    const int*   __restrict__ row,
    const int*   __restrict__ col,
    const float* __restrict__ adj)
{
    int i = blockIdx.x * blockDim.x + threadIdx.x;
    int e = i * 2;
    if (e >= EE) return;
    int2   r2 = *(const int2*)&row[e];
    int2   c2 = *(const int2*)&col[e];
    float2 a2 = *(const float2*)&adj[e];
    int p0 = g_off[r2.x] + atomicAdd(&g_cnt2[r2.x], 1);
    g_ecol[p0] = make_uint2((unsigned)(c2.x * 32), __float_as_uint(a2.x));
    int p1 = g_off[r2.y] + atomicAdd(&g_cnt2[r2.y], 1);
    g_ecol[p1] = make_uint2((unsigned)(c2.y * 32), __float_as_uint(a2.y));
}

// ---------------- kernel 5: fused attention + SpMM, warp per node ----------------
__global__ __launch_bounds__(128) void fused_kernel() {
    int w = threadIdx.x >> 5, lane = threadIdx.x & 31;
    int i = blockIdx.x * 4 + w;
    if (i >= NN) return;
    int start = g_off[i], end = g_off[i + 1];

    // a_row[i]: 64 B, broadcast load into registers (all lanes same address)
    uint4 ar[4];
    const uint4* arp = (const uint4*)&g_arowh[i * 16];
#pragma unroll
    for (int q = 0; q < 4; q++) ar[q] = arp[q];

    // ---- loop 1: per-edge attention, denominator in registers ----
    float degacc = 0.f;
    for (int base = start; base < end; base += 32) {
        int k = base + lane;
        if (k < end) {
            uint2 ca = g_ecol[k];                          // {col*32, adj bits}
            const uint4* ac4 = (const uint4*)&g_acolh[(ca.x >> 5) * 16];
            float dot = 0.f;
#pragma unroll
            for (int q = 0; q < 4; q++) {
                uint4 A = ar[q], B = ac4[q];
                const __half2* ah = (const __half2*)&A;
                const __half2* bh = (const __half2*)&B;
#pragma unroll
                for (int j = 0; j < 4; j++) {
                    float2 a = __half22float2(ah[j]);
                    float2 b = __half22float2(bh[j]);
                    dot += a.x * b.x + a.y * b.y;
                }
            }
            float s = dot * 0.17677669529663687f;          // rsqrt(32)
            if (s < 0.f) s *= 0.2f;                        // leaky relu
            float ea = __expf(s);
            g_ea[k] = ea;
            degacc += ea;
        }
    }
#pragma unroll
    for (int s = 16; s > 0; s >>= 1) degacc += __shfl_xor_sync(0xffffffffu, degacc, s);
    float inv = 1.f / (degacc + 1e-15f);

    // ---- loop 2: x gather accumulate ----
    const uint2* x2 = (const uint2*)g_xh;      // one uint2 = 4 dims; row = 32 uint2
    float a0 = 0.f, a1 = 0.f, a2 = 0.f, a3 = 0.f;
    int base = start;
    for (; base + 32 <= end; base += 32) {
        uint2 ca = g_ecol[base + lane];
        float ea = g_ea[base + lane];
        float myval = (__uint_as_float(ca.y) + ea * inv) * 0.5f;
        int   mycol = (int)ca.x;
#pragma unroll 8
        for (int j = 0; j < 32; j++) {
            float v  = __shfl_sync(0xffffffffu, myval, j);
            int   cb = __shfl_sync(0xffffffffu, mycol, j);
            uint2 xv = x2[cb + lane];
            __half2 xa = *reinterpret_cast<__half2*>(&xv.x);
            __half2 xb = *reinterpret_cast<__half2*>(&xv.y);
            float2 fa = __half22float2(xa);
            float2 fb = __half22float2(xb);
            a0 += v * fa.x; a1 += v * fa.y;
            a2 += v * fb.x; a3 += v * fb.y;
        }
    }
    if (base < end) {
        int k = base + lane;
        float myval = 0.f;
        int   mycol = 0;
        if (k < end) {
            uint2 ca = g_ecol[k];
            float ea = g_ea[k];
            myval = (__uint_as_float(ca.y) + ea * inv) * 0.5f;
            mycol = (int)ca.x;
        }
        int m = end - base;
        for (int j = 0; j < m; j++) {
            float v  = __shfl_sync(0xffffffffu, myval, j);
            int   cb = __shfl_sync(0xffffffffu, mycol, j);
            uint2 xv = x2[cb + lane];
            __half2 xa = *reinterpret_cast<__half2*>(&xv.x);
            __half2 xb = *reinterpret_cast<__half2*>(&xv.y);
            float2 fa = __half22float2(xa);
            float2 fb = __half22float2(xb);
            a0 += v * fa.x; a1 += v * fa.y;
            a2 += v * fb.x; a3 += v * fb.y;
        }
    }

    uint2 o;
    __half2 o0 = __floats2half2_rn(a0, a1);
    __half2 o1 = __floats2half2_rn(a2, a3);
    o.x = *reinterpret_cast<unsigned*>(&o0);
    o.y = *reinterpret_cast<unsigned*>(&o1);
    *(uint2*)&g_hh[i * 64 + lane * 2] = o;
}

// ---------------- kernel 6: out = h @ W_x + b_x (HMMA m16n8k16) ----------------
// BM=128, BN=128, single K=128 pass. 256 threads (8 warps), warp tile 32x64.
#define LDA 136
#define LDB 136
__global__ __launch_bounds__(256) void gemm_kernel(
    const float* __restrict__ bias,
    float* __restrict__ out)
{
    extern __shared__ __half sm[];
    __half* As = sm;                 // [128][LDA]
    __half* Bs = sm + 128 * LDA;     // [128][LDB]

    int tid = threadIdx.x;
    int m0  = blockIdx.y * 128;
    int n0g = blockIdx.x * 128;

    // load A: h rows m0..m0+127 (256 B each = 16 uint4)
    const uint4* hsrc = (const uint4*)g_hh;
#pragma unroll
    for (int p = 0; p < 8; p++) {
        int idx = tid + 256 * p;
        int r = idx >> 4, seg = idx & 15;
        uint4 v = make_uint4(0u, 0u, 0u, 0u);
        if (m0 + r < NN) v = hsrc[(m0 + r) * 16 + seg];
        *(uint4*)&As[r * LDA + seg * 8] = v;
    }
    // load B: W rows k=0..127, cols n0g..n0g+127 (16 uint4 per row slice)
    const uint4* wsrc = (const uint4*)g_Wh;
#pragma unroll
    for (int p = 0; p < 8; p++) {
        int idx = tid + 256 * p;
        int kk = idx >> 4, seg = idx & 15;
        uint4 v = wsrc[kk * 32 + (n0g >> 3) + seg];
        *(uint4*)&Bs[kk * LDB + seg * 8] = v;
    }
    __syncthreads();

    int w    = tid >> 5;
    int lane = tid & 31;
    int wm = (w & 3) * 32;       // warp row offset
    int wn = (w >> 2) * 64;      // warp col offset

    float acc[2][8][4];
#pragma unroll
    for (int mt = 0; mt < 2; mt++)
#pragma unroll
        for (int nt = 0; nt < 8; nt++)
#pragma unroll
            for (int q = 0; q < 4; q++) acc[mt][nt][q] = 0.f;

#pragma unroll
    for (int ks = 0; ks < 8; ks++) {
        int k0 = ks * 16;
        unsigned afr[2][4];
#pragma unroll
        for (int mt = 0; mt < 2; mt++) {
            int r = wm + mt * 16 + (lane & 15);
            int c = k0 + (lane >> 4) * 8;
            unsigned addr = (unsigned)__cvta_generic_to_shared(&As[r * LDA + c]);
            asm volatile("ldmatrix.sync.aligned.m8n8.x4.shared.b16 {%0,%1,%2,%3}, [%4];"
                : "=r"(afr[mt][0]), "=r"(afr[mt][1]), "=r"(afr[mt][2]), "=r"(afr[mt][3])
                : "r"(addr));
        }
        unsigned bfr[8][2];
#pragma unroll
        for (int ntp = 0; ntp < 4; ntp++) {
            int kk = k0 + (lane & 15);
            int nn = wn + ntp * 16 + (lane >> 4) * 8;
            unsigned addr = (unsigned)__cvta_generic_to_shared(&Bs[kk * LDB + nn]);
            unsigned r0, r1, r2, r3;
            asm volatile("ldmatrix.sync.aligned.m8n8.x4.trans.shared.b16 {%0,%1,%2,%3}, [%4];"
                : "=r"(r0), "=r"(r1), "=r"(r2), "=r"(r3) : "r"(addr));
            bfr[ntp * 2][0] = r0;     bfr[ntp * 2][1] = r1;
            bfr[ntp * 2 + 1][0] = r2; bfr[ntp * 2 + 1][1] = r3;
        }
#pragma unroll
        for (int mt = 0; mt < 2; mt++)
#pragma unroll
            for (int nt = 0; nt < 8; nt++) {
                asm volatile(
                    "mma.sync.aligned.m16n8k16.row.col.f32.f16.f16.f32 "
                    "{%0,%1,%2,%3}, {%4,%5,%6,%7}, {%8,%9}, {%0,%1,%2,%3};"
                    : "+f"(acc[mt][nt][0]), "+f"(acc[mt][nt][1]),
                      "+f"(acc[mt][nt][2]), "+f"(acc[mt][nt][3])
                    : "r"(afr[mt][0]), "r"(afr[mt][1]), "r"(afr[mt][2]), "r"(afr[mt][3]),
                      "r"(bfr[nt][0]), "r"(bfr[nt][1]));
            }
    }

    // epilogue
    int g   = lane >> 2;
    int tig = lane & 3;
#pragma unroll
    for (int mt = 0; mt < 2; mt++) {
#pragma unroll
        for (int nt = 0; nt < 8; nt++) {
            int colg = n0g + wn + nt * 8 + tig * 2;
            float b0 = bias[colg], b1 = bias[colg + 1];
            int r0 = m0 + wm + mt * 16 + g;
            if (r0 < NN) {
                float2 v0 = make_float2(acc[mt][nt][0] + b0, acc[mt][nt][1] + b1);
                *(float2*)&out[r0 * DOUT + colg] = v0;
            }
            int r1 = r0 + 8;
            if (r1 < NN) {
                float2 v1 = make_float2(acc[mt][nt][2] + b0, acc[mt][nt][3] + b1);
                *(float2*)&out[r1 * DOUT + colg] = v1;
            }
        }
    }
}

// ---------------- launch ----------------
extern "C" void kernel_launch(void* const* d_in, const int* in_sizes, int n_in,
                              void* d_out, int out_size)
{
    const float* x    = (const float*)d_in[0];
    const int*   row  = (const int*)  d_in[1];
    const int*   col  = (const int*)  d_in[2];
    const float* adj  = (const float*)d_in[3];
    const float* Wr   = (const float*)d_in[4];
    const float* Wc   = (const float*)d_in[5];
    const float* Wx   = (const float*)d_in[6];
    const float* bx   = (const float*)d_in[7];
    float* out = (float*)d_out;

    // one-time resources (no device memory; identical captured work every call)
    static cudaStream_t s1 = nullptr;
    static cudaEvent_t evFork = nullptr, evJoin = nullptr;
    static bool smem_set = false;
    const int GEMM_SMEM = (128 * LDA + 128 * LDB) * 2;   // 69632 B
    if (!s1) {
        cudaStreamCreateWithFlags(&s1, cudaStreamNonBlocking);
        cudaEventCreateWithFlags(&evFork, cudaEventDisableTiming);
        cudaEventCreateWithFlags(&evJoin, cudaEventDisableTiming);
    }
    if (!smem_set) {
        cudaFuncSetAttribute(gemm_kernel, cudaFuncAttributeMaxDynamicSharedMemorySize, GEMM_SMEM);
        smem_set = true;
    }

    // fork: proj on s1 runs concurrently with init+hist+scan+scatter chain
    cudaEventRecord(evFork, 0);
    cudaStreamWaitEvent(s1, evFork, 0);
    proj_kernel<<<(NN + PROJ_NODES - 1) / PROJ_NODES, 256, 0, s1>>>(x, Wr, Wc);
    cudaEventRecord(evJoin, s1);

    init_kernel<<<(NN + 255) / 256, 256>>>(Wx);
    hist_kernel<<<(EE / 4 + 255) / 256, 256>>>(row);
    scanA_kernel<<<NBLK, 1024>>>();
    scanB_kernel<<<1, 64>>>();
    scanC_kernel<<<NBLK, 1024>>>();
    scatter_kernel<<<(EE / 2 + 255) / 256, 256>>>(row, col, adj);

    // join: fused attention+spmm needs proj outputs + CSR
    cudaStreamWaitEvent(0, evJoin, 0);
    fused_kernel<<<(NN + 3) / 4, 128>>>();
    gemm_kernel<<<dim3(DOUT / 128, (NN + 127) / 128), 256, GEMM_SMEM>>>(bx, out);
}